// round 10
// baseline (speedup 1.0000x reference)
#include <cuda_runtime.h>
#include <cuda_fp16.h>
#include <math.h>
#include <stdint.h>

#define B_   4
#define S_   4096
#define D_   1024
#define ROWS (B_ * S_)        // 16384
#define NSEG 128
#define SEGLEN (S_ / NSEG)    // 32

// ---------------- scratch (static device globals; no allocations) -------------
__device__ __half sc_h [(size_t)ROWS * D_];      // LN1 output (fp16)
__device__ __half sc_g [(size_t)ROWS * D_];      // sigmoid gate (fp16)
__device__ __half sc_v [(size_t)ROWS * D_];      // value (fp16)
__device__ float  sc_x [(size_t)ROWS * D_];
__device__ __half sc_h2[(size_t)ROWS * D_];      // LN2 output (fp16)
__device__ __half sc_u [(size_t)ROWS * 4 * D_];  // gelu out (fp16)
__device__ float  sc_pg [(size_t)B_ * NSEG * D_];
__device__ float  sc_pgv[(size_t)B_ * NSEG * D_];
__device__ __half sc_gwt[(size_t)D_ * D_];       // gate_w^T  [N,K] fp16
__device__ __half sc_vwt[(size_t)D_ * D_];       // value_w^T [N,K] fp16
__device__ __half sc_w1t[(size_t)4 * D_ * D_];   // ffn_w1^T  fp16
__device__ __half sc_w2t[(size_t)D_ * 4 * D_];   // ffn_w2^T  fp16

// =================== helpers ====================================================
__device__ __forceinline__ uint32_t smem_u32(const void* p) {
    uint32_t a;
    asm("{ .reg .u64 t; cvta.to.shared.u64 t, %1; cvt.u32.u64 %0, t; }"
        : "=r"(a) : "l"(p));
    return a;
}

#define CP_COMMIT() asm volatile("cp.async.commit_group;" ::: "memory")
template <int N> __device__ __forceinline__ void cp_wait() {
    asm volatile("cp.async.wait_group %0;" :: "n"(N) : "memory");
}
__device__ __forceinline__ void cpasync16(uint32_t saddr, const void* g) {
    asm volatile("cp.async.cg.shared.global [%0], [%1], 16;"
                 :: "r"(saddr), "l"(g) : "memory");
}

// mma.sync m16n8k16 fp16 inputs, fp32 accumulate
__device__ __forceinline__ void mma_f16(float* c, const uint32_t* a, const uint32_t* b) {
    asm volatile(
        "mma.sync.aligned.m16n8k16.row.col.f32.f16.f16.f32 "
        "{%0,%1,%2,%3}, {%4,%5,%6,%7}, {%8,%9}, {%0,%1,%2,%3};"
        : "+f"(c[0]), "+f"(c[1]), "+f"(c[2]), "+f"(c[3])
        : "r"(a[0]), "r"(a[1]), "r"(a[2]), "r"(a[3]), "r"(b[0]), "r"(b[1]));
}

__device__ __forceinline__ void ldm4(uint32_t* r, uint32_t a) {
    asm volatile("ldmatrix.sync.aligned.m8n8.x4.shared.b16 {%0,%1,%2,%3}, [%4];"
                 : "=r"(r[0]), "=r"(r[1]), "=r"(r[2]), "=r"(r[3]) : "r"(a));
}

__device__ __forceinline__ void store2(float* p, float x, float y) {
    float2 t; t.x = x; t.y = y; *(float2*)p = t;
}
__device__ __forceinline__ void store2(__half* p, float x, float y) {
    *(__half2*)p = __floats2half2_rn(x, y);
}

// =================== mma.sync FP16 GEMM: 256x128 CTA tile ======================
// C[M,N] = A[M,K] @ Bt[N,K]^T (+bias, epilogue). A, Bt fp16; accum fp32.
// 256 threads (8 warps, 4x2), 64x64 warp tile, BK=64 halfs, 3-stage pipeline,
// ldmatrix fragments double-buffered across k-slices. 1 CTA/SM.
enum { EPI_NONE = 0, EPI_SIGMOID = 1, EPI_GELU = 2, EPI_ADD = 3 };

#define TILEA_B  32768                 // 256 rows * 128 bytes
#define TILEB_B  16384                 // 128 rows * 128 bytes
#define STAGE_B  (TILEA_B + TILEB_B)   // 49152
#define NSTG     3
#define GEMM_SMEM (NSTG * STAGE_B)     // 147456 bytes

template <int EPI, typename OutT>
__global__ __launch_bounds__(256, 1) void gemm_mma(
    const __half* __restrict__ A, const __half* __restrict__ Bt,
    const float* __restrict__ bias, const float* __restrict__ addsrc,
    OutT* __restrict__ C, int M, int N, int K)
{
    extern __shared__ char smraw[];
    uint32_t smb = smem_u32(smraw);

    int tid  = threadIdx.x;
    int warp = tid >> 5, lane = tid & 31;
    int g = lane >> 2, t = lane & 3;
    int wm = warp >> 1, wn = warp & 1;          // 4 x 2 warp grid, 64x64 tiles
    int row0 = blockIdx.y * 256;
    int col0 = blockIdx.x * 128;
    int KCH  = K >> 6;                          // K chunks of 64 halfs (128B)

    // ---- gmem->smem load mapping: 256 threads, rows lr+32i, 16B chunk lc -------
    int lr = tid >> 3;          // 0..31
    int lc = tid & 7;           // 0..7
    uint32_t stA[8], stB[4];
    #pragma unroll
    for (int i = 0; i < 8; i++) {
        int row = lr + 32 * i;  // 0..255
        stA[i] = (uint32_t)(row * 128 + ((lc ^ (row & 7)) << 4));
    }
    #pragma unroll
    for (int i = 0; i < 4; i++) {
        int row = lr + 32 * i;  // 0..127
        stB[i] = (uint32_t)(row * 128 + ((lc ^ (row & 7)) << 4));
    }
    const __half* gA = A  + (size_t)(row0 + lr) * K + lc * 8;
    const __half* gB = Bt + (size_t)(col0 + lr) * K + lc * 8;

    // ---- ldmatrix per-lane address offsets (k-slice 0; advance via ^(ks<<5)) ---
    uint32_t rxor = (uint32_t)(lane & 7) << 4;
    uint32_t aoff[4], boff[4];
    #pragma unroll
    for (int i = 0; i < 4; i++) {
        int arow = wm * 64 + i * 16 + ((lane >> 3) & 1) * 8 + (lane & 7);
        aoff[i] = (uint32_t)arow * 128 + (((uint32_t)((lane >> 4) & 1) << 4) ^ rxor);
    }
    #pragma unroll
    for (int jp = 0; jp < 4; jp++) {
        int brow = wn * 64 + jp * 16 + (((lane >> 4) & 1) << 3) + (lane & 7);
        boff[jp] = (uint32_t)brow * 128 + (((uint32_t)((lane >> 3) & 1) << 4) ^ rxor);
    }

    float c[4][8][4];
    #pragma unroll
    for (int i = 0; i < 4; i++)
        #pragma unroll
        for (int j = 0; j < 8; j++)
            #pragma unroll
            for (int q = 0; q < 4; q++) c[i][j][q] = 0.f;

    // prologue: stages 0,1
    #pragma unroll
    for (int s = 0; s < 2; s++) {
        uint32_t ab = smb + s * STAGE_B;
        uint32_t bb = ab + TILEA_B;
        #pragma unroll
        for (int i = 0; i < 8; i++)
            cpasync16(ab + stA[i], gA + (size_t)i * 32 * K + s * 64);
        #pragma unroll
        for (int i = 0; i < 4; i++)
            cpasync16(bb + stB[i], gB + (size_t)i * 32 * K + s * 64);
        CP_COMMIT();
    }

    for (int kc = 0; kc < KCH; kc++) {
        cp_wait<1>();
        __syncthreads();

        if (kc + 2 < KCH) {
            int s2 = (kc + 2) % NSTG;
            uint32_t ab = smb + s2 * STAGE_B;
            uint32_t bb = ab + TILEA_B;
            #pragma unroll
            for (int i = 0; i < 8; i++)
                cpasync16(ab + stA[i], gA + (size_t)i * 32 * K + (kc + 2) * 64);
            #pragma unroll
            for (int i = 0; i < 4; i++)
                cpasync16(bb + stB[i], gB + (size_t)i * 32 * K + (kc + 2) * 64);
        }
        CP_COMMIT();

        uint32_t sAst = smb + (kc % NSTG) * STAGE_B;
        uint32_t sBst = sAst + TILEA_B;

        uint32_t af[2][4][4], bf[2][4][4];
        #pragma unroll
        for (int i = 0; i < 4; i++) ldm4(af[0][i], sAst + aoff[i]);
        #pragma unroll
        for (int jp = 0; jp < 4; jp++) ldm4(bf[0][jp], sBst + boff[jp]);

        #pragma unroll
        for (int ks = 0; ks < 4; ks++) {
            int cb = ks & 1, nb = cb ^ 1;
            if (ks < 3) {
                uint32_t kx = (uint32_t)(ks + 1) << 5;
                #pragma unroll
                for (int i = 0; i < 4; i++) ldm4(af[nb][i], sAst + (aoff[i] ^ kx));
                #pragma unroll
                for (int jp = 0; jp < 4; jp++) ldm4(bf[nb][jp], sBst + (boff[jp] ^ kx));
            }
            #pragma unroll
            for (int i = 0; i < 4; i++)
                #pragma unroll
                for (int jp = 0; jp < 4; jp++) {
                    mma_f16(c[i][2 * jp],     af[cb][i], &bf[cb][jp][0]);
                    mma_f16(c[i][2 * jp + 1], af[cb][i], &bf[cb][jp][2]);
                }
        }
    }

    // ---- epilogue ---------------------------------------------------------------
    #pragma unroll
    for (int i = 0; i < 4; i++) {
        int rlo = row0 + wm * 64 + i * 16 + g;
        #pragma unroll
        for (int j = 0; j < 8; j++) {
            int col = col0 + wn * 64 + j * 8 + 2 * t;
            float2 bv = *(const float2*)(bias + col);
            float lox = c[i][j][0] + bv.x, loy = c[i][j][1] + bv.y;
            float hix = c[i][j][2] + bv.x, hiy = c[i][j][3] + bv.y;
            size_t olo = (size_t)rlo * N + col;
            size_t ohi = olo + (size_t)8 * N;
            if (EPI == EPI_SIGMOID) {
                lox = 1.f / (1.f + __expf(-lox)); loy = 1.f / (1.f + __expf(-loy));
                hix = 1.f / (1.f + __expf(-hix)); hiy = 1.f / (1.f + __expf(-hiy));
            } else if (EPI == EPI_GELU) {
                lox = 0.5f * lox * (1.f + erff(lox * 0.70710678118654752f));
                loy = 0.5f * loy * (1.f + erff(loy * 0.70710678118654752f));
                hix = 0.5f * hix * (1.f + erff(hix * 0.70710678118654752f));
                hiy = 0.5f * hiy * (1.f + erff(hiy * 0.70710678118654752f));
            } else if (EPI == EPI_ADD) {
                float2 a0 = *(const float2*)(addsrc + olo);
                float2 a1 = *(const float2*)(addsrc + ohi);
                lox += a0.x; loy += a0.y; hix += a1.x; hiy += a1.y;
            }
            store2(C + olo, lox, loy);
            store2(C + ohi, hix, hiy);
        }
    }
}

// =================== transpose (f32 -> f16): in[R,C] -> out[C,R] ===============
__global__ __launch_bounds__(256) void transpose_kernel(
    const float* __restrict__ in, __half* __restrict__ out, int R, int C)
{
    __shared__ float t[32][33];
    int bx = blockIdx.x * 32, by = blockIdx.y * 32;
    int tx = threadIdx.x & 31, ty = threadIdx.x >> 5;
    #pragma unroll
    for (int i = 0; i < 32; i += 8)
        t[ty + i][tx] = in[(size_t)(by + ty + i) * C + bx + tx];
    __syncthreads();
    #pragma unroll
    for (int i = 0; i < 32; i += 8)
        out[(size_t)(bx + ty + i) * R + by + tx] = __float2half_rn(t[tx][ty + i]);
}

// =================== LayerNorm (f32 in, f16 out) — used for LN1 ================
__global__ __launch_bounds__(256) void ln_kernel(
    const float* __restrict__ x, const float* __restrict__ gamma,
    const float* __restrict__ beta, __half* __restrict__ out)
{
    int row = blockIdx.x;
    int tid = threadIdx.x;
    const float4* xr = (const float4*)(x + (size_t)row * D_);
    float4 v = xr[tid];

    float s  = v.x + v.y + v.z + v.w;
    float sq = v.x*v.x + v.y*v.y + v.z*v.z + v.w*v.w;

    __shared__ float red0[8], red1[8];
    #pragma unroll
    for (int o = 16; o > 0; o >>= 1) {
        s  += __shfl_xor_sync(0xffffffffu, s,  o);
        sq += __shfl_xor_sync(0xffffffffu, sq, o);
    }
    if ((tid & 31) == 0) { red0[tid >> 5] = s; red1[tid >> 5] = sq; }
    __syncthreads();
    if (tid < 32) {
        s  = (tid < 8) ? red0[tid] : 0.f;
        sq = (tid < 8) ? red1[tid] : 0.f;
        #pragma unroll
        for (int o = 4; o > 0; o >>= 1) {
            s  += __shfl_xor_sync(0xffffffffu, s,  o);
            sq += __shfl_xor_sync(0xffffffffu, sq, o);
        }
        if (tid == 0) {
            float mu = s * (1.0f / D_);
            float var = sq * (1.0f / D_) - mu * mu;
            red0[0] = mu;
            red1[0] = rsqrtf(var + 1e-5f);
        }
    }
    __syncthreads();
    float mu = red0[0], rstd = red1[0];

    float4 gv = ((const float4*)gamma)[tid];
    float4 bv = ((const float4*)beta)[tid];
    __half2* orow = (__half2*)(out + (size_t)row * D_);
    orow[tid * 2]     = __floats2half2_rn((v.x - mu) * rstd * gv.x + bv.x,
                                          (v.y - mu) * rstd * gv.y + bv.y);
    orow[tid * 2 + 1] = __floats2half2_rn((v.z - mu) * rstd * gv.z + bv.z,
                                          (v.w - mu) * rstd * gv.w + bv.w);
}

// =================== cumsum passes (g, v in fp16) ==============================
__global__ __launch_bounds__(256) void cums_partial(
    const __half* __restrict__ g, const __half* __restrict__ v,
    float* __restrict__ pg, float* __restrict__ pgv)
{
    int bs  = blockIdx.x;            // b*NSEG + seg
    int b   = bs >> 7;
    int seg = bs & 127;
    int d   = (blockIdx.y * 256 + threadIdx.x) * 2;   // half2 lane
    size_t base = ((size_t)b * S_ + (size_t)seg * SEGLEN) * D_ + d;

    float2 sg = {0.f, 0.f}, sgv = {0.f, 0.f};
    #pragma unroll 4
    for (int s = 0; s < SEGLEN; s++) {
        float2 g2 = __half22float2(*(const __half2*)(g + base + (size_t)s * D_));
        float2 v2 = __half22float2(*(const __half2*)(v + base + (size_t)s * D_));
        sg.x  += g2.x;        sg.y  += g2.y;
        sgv.x += g2.x * v2.x; sgv.y += g2.y * v2.y;
    }
    size_t o = (size_t)bs * D_ + d;
    *(float2*)(pg  + o) = sg;
    *(float2*)(pgv + o) = sgv;
}

__global__ __launch_bounds__(256) void cums_scan(
    float* __restrict__ pg, float* __restrict__ pgv)
{
    int idx = blockIdx.x * 256 + threadIdx.x;  // 0 .. B_*D_-1
    int b = idx / D_;
    int d = idx % D_;
    float rg = 0.f, rgv = 0.f;
    for (int seg = 0; seg < NSEG; seg++) {
        size_t o = ((size_t)b * NSEG + seg) * D_ + d;
        float tg = pg[o], tgv = pgv[o];
        pg[o]  = rg;
        pgv[o] = rgv;
        rg  += tg;
        rgv += tgv;
    }
}

// ---- fused: inclusive cumsum-apply + residual + LayerNorm2 (f16 out) ----------
__global__ __launch_bounds__(256) void cums_ln2(
    const __half* __restrict__ g, const __half* __restrict__ v,
    const float* __restrict__ x,
    const float* __restrict__ pg, const float* __restrict__ pgv,
    const float* __restrict__ gamma, const float* __restrict__ beta,
    float* __restrict__ xout, __half* __restrict__ h2)
{
    int bs  = blockIdx.x;            // b*NSEG + seg
    int b   = bs >> 7;
    int seg = bs & 127;
    int tid = threadIdx.x;
    int wid = tid >> 5, lid = tid & 31;

    size_t rowbase = (size_t)b * S_ + (size_t)seg * SEGLEN;
    size_t po = (size_t)bs * D_ + tid * 4;
    float4 rg  = *(const float4*)(pg  + po);
    float4 rgv = *(const float4*)(pgv + po);
    float4 gm  = ((const float4*)gamma)[tid];
    float4 bt  = ((const float4*)beta)[tid];

    __shared__ float red0[8], red1[8], bmu[2];

    for (int s = 0; s < SEGLEN; s++) {
        size_t o = (rowbase + s) * D_ + tid * 4;
        float2 ga = __half22float2(*(const __half2*)(g + o));
        float2 gb = __half22float2(*(const __half2*)(g + o + 2));
        float2 va = __half22float2(*(const __half2*)(v + o));
        float2 vb = __half22float2(*(const __half2*)(v + o + 2));
        float4 x4 = *(const float4*)(x + o);

        rgv.x += ga.x * va.x;  rg.x += ga.x;
        rgv.y += ga.y * va.y;  rg.y += ga.y;
        rgv.z += gb.x * vb.x;  rg.z += gb.x;
        rgv.w += gb.y * vb.y;  rg.w += gb.y;

        float4 xo;
        xo.x = x4.x + rgv.x / (rg.x + 1e-6f);
        xo.y = x4.y + rgv.y / (rg.y + 1e-6f);
        xo.z = x4.z + rgv.z / (rg.z + 1e-6f);
        xo.w = x4.w + rgv.w / (rg.w + 1e-6f);
        *(float4*)(xout + o) = xo;

        float ss = xo.x + xo.y + xo.z + xo.w;
        float sq = xo.x*xo.x + xo.y*xo.y + xo.z*xo.z + xo.w*xo.w;
        #pragma unroll
        for (int of = 16; of > 0; of >>= 1) {
            ss += __shfl_xor_sync(0xffffffffu, ss, of);
            sq += __shfl_xor_sync(0xffffffffu, sq, of);
        }
        if (lid == 0) { red0[wid] = ss; red1[wid] = sq; }
        __syncthreads();
        if (tid < 32) {
            float a = (tid < 8) ? red0[tid] : 0.f;
            float q = (tid < 8) ? red1[tid] : 0.f;
            #pragma unroll
            for (int of = 4; of > 0; of >>= 1) {
                a += __shfl_xor_sync(0xffffffffu, a, of);
                q += __shfl_xor_sync(0xffffffffu, q, of);
            }
            if (tid == 0) {
                float mu = a * (1.0f / D_);
                float var = q * (1.0f / D_) - mu * mu;
                bmu[0] = mu;
                bmu[1] = rsqrtf(var + 1e-5f);
            }
        }
        __syncthreads();
        float mu = bmu[0], rstd = bmu[1];

        __half2* hrow = (__half2*)(h2 + (rowbase + s) * D_);
        hrow[tid * 2]     = __floats2half2_rn((xo.x - mu) * rstd * gm.x + bt.x,
                                              (xo.y - mu) * rstd * gm.y + bt.y);
        hrow[tid * 2 + 1] = __floats2half2_rn((xo.z - mu) * rstd * gm.z + bt.z,
                                              (xo.w - mu) * rstd * gm.w + bt.w);
    }
}

// =================== launch ====================================================
extern "C" void kernel_launch(void* const* d_in, const int* in_sizes, int n_in,
                              void* d_out, int out_size)
{
    const float* x       = (const float*)d_in[0];
    const float* ln1_g   = (const float*)d_in[1];
    const float* ln1_b   = (const float*)d_in[2];
    const float* ln2_g   = (const float*)d_in[3];
    const float* ln2_b   = (const float*)d_in[4];
    const float* gate_w  = (const float*)d_in[5];
    const float* gate_b  = (const float*)d_in[6];
    const float* value_w = (const float*)d_in[7];
    const float* value_b = (const float*)d_in[8];
    const float* ffn_w1  = (const float*)d_in[9];
    const float* ffn_b1  = (const float*)d_in[10];
    const float* ffn_w2  = (const float*)d_in[11];
    const float* ffn_b2  = (const float*)d_in[12];
    float* out = (float*)d_out;

    __half *h, *h2, *u, *gwt, *vwt, *w1t, *w2t, *g, *v;
    float *xn, *pg, *pgv;
    cudaGetSymbolAddress((void**)&h,   sc_h);
    cudaGetSymbolAddress((void**)&g,   sc_g);
    cudaGetSymbolAddress((void**)&v,   sc_v);
    cudaGetSymbolAddress((void**)&xn,  sc_x);
    cudaGetSymbolAddress((void**)&h2,  sc_h2);
    cudaGetSymbolAddress((void**)&u,   sc_u);
    cudaGetSymbolAddress((void**)&pg,  sc_pg);
    cudaGetSymbolAddress((void**)&pgv, sc_pgv);
    cudaGetSymbolAddress((void**)&gwt, sc_gwt);
    cudaGetSymbolAddress((void**)&vwt, sc_vwt);
    cudaGetSymbolAddress((void**)&w1t, sc_w1t);
    cudaGetSymbolAddress((void**)&w2t, sc_w2t);

    cudaFuncSetAttribute(gemm_mma<EPI_SIGMOID, __half>, cudaFuncAttributeMaxDynamicSharedMemorySize, GEMM_SMEM);
    cudaFuncSetAttribute(gemm_mma<EPI_NONE, __half>,    cudaFuncAttributeMaxDynamicSharedMemorySize, GEMM_SMEM);
    cudaFuncSetAttribute(gemm_mma<EPI_GELU, __half>,    cudaFuncAttributeMaxDynamicSharedMemorySize, GEMM_SMEM);
    cudaFuncSetAttribute(gemm_mma<EPI_ADD, float>,      cudaFuncAttributeMaxDynamicSharedMemorySize, GEMM_SMEM);

    // 0. transpose weights to [N,K] fp16
    transpose_kernel<<<dim3(D_/32, D_/32),   256>>>(gate_w,  gwt, D_, D_);
    transpose_kernel<<<dim3(D_/32, D_/32),   256>>>(value_w, vwt, D_, D_);
    transpose_kernel<<<dim3(4*D_/32, D_/32), 256>>>(ffn_w1,  w1t, D_, 4*D_);
    transpose_kernel<<<dim3(D_/32, 4*D_/32), 256>>>(ffn_w2,  w2t, 4*D_, D_);

    // 1. h = LN1(x)  (fp16)
    ln_kernel<<<ROWS, 256>>>(x, ln1_g, ln1_b, h);

    // 2/3. gate + value GEMMs (fp16 outputs)
    dim3 gridDD(D_ / 128, ROWS / 256);
    gemm_mma<EPI_SIGMOID, __half><<<gridDD, 256, GEMM_SMEM>>>(h, gwt, gate_b, nullptr, g, ROWS, D_, D_);
    gemm_mma<EPI_NONE, __half>   <<<gridDD, 256, GEMM_SMEM>>>(h, vwt, value_b, nullptr, v, ROWS, D_, D_);

    // 4. memory residual + LN2 (fused)
    cums_partial<<<dim3(B_ * NSEG, D_ / 512), 256>>>(g, v, pg, pgv);
    cums_scan<<<(B_ * D_) / 256, 256>>>(pg, pgv);
    cums_ln2<<<B_ * NSEG, 256>>>(g, v, x, pg, pgv, ln2_g, ln2_b, xn, h2);

    // 6. u = gelu(h2 @ W1 + b1)  (fp16 out)
    dim3 gridFF1(4 * D_ / 128, ROWS / 256);
    gemm_mma<EPI_GELU, __half><<<gridFF1, 256, GEMM_SMEM>>>(h2, w1t, ffn_b1, nullptr, u, ROWS, 4 * D_, D_);

    // 7. out = x_new + u @ W2 + b2
    gemm_mma<EPI_ADD, float><<<gridDD, 256, GEMM_SMEM>>>(u, w2t, ffn_b2, xn, out, ROWS, D_, 4 * D_);
}

// round 11
// speedup vs baseline: 1.1618x; 1.1618x over previous
#include <cuda_runtime.h>
#include <cuda_fp16.h>
#include <math.h>
#include <stdint.h>

#define B_   4
#define S_   4096
#define D_   1024
#define ROWS (B_ * S_)        // 16384
#define NSEG 128
#define SEGLEN (S_ / NSEG)    // 32

// ---------------- scratch (static device globals; no allocations) -------------
__device__ __half sc_h [(size_t)ROWS * D_];      // LN1 output (fp16)
__device__ __half sc_g [(size_t)ROWS * D_];      // sigmoid gate (fp16)
__device__ __half sc_v [(size_t)ROWS * D_];      // value (fp16)
__device__ __half sc_x [(size_t)ROWS * D_];      // x after memory residual (fp16)
__device__ __half sc_h2[(size_t)ROWS * D_];      // LN2 output (fp16)
__device__ __half sc_u [(size_t)ROWS * 4 * D_];  // gelu out (fp16)
__device__ float  sc_pg [(size_t)B_ * NSEG * D_];
__device__ float  sc_pgv[(size_t)B_ * NSEG * D_];
__device__ __half sc_gwt[(size_t)D_ * D_];       // gate_w^T  [N,K] fp16
__device__ __half sc_vwt[(size_t)D_ * D_];       // value_w^T [N,K] fp16
__device__ __half sc_w1t[(size_t)4 * D_ * D_];   // ffn_w1^T  fp16
__device__ __half sc_w2t[(size_t)D_ * 4 * D_];   // ffn_w2^T  fp16

// =================== helpers ====================================================
__device__ __forceinline__ uint32_t smem_u32(const void* p) {
    uint32_t a;
    asm("{ .reg .u64 t; cvta.to.shared.u64 t, %1; cvt.u32.u64 %0, t; }"
        : "=r"(a) : "l"(p));
    return a;
}

#define CP_COMMIT() asm volatile("cp.async.commit_group;" ::: "memory")
template <int N> __device__ __forceinline__ void cp_wait() {
    asm volatile("cp.async.wait_group %0;" :: "n"(N) : "memory");
}
__device__ __forceinline__ void cpasync16(uint32_t saddr, const void* g) {
    asm volatile("cp.async.cg.shared.global [%0], [%1], 16;"
                 :: "r"(saddr), "l"(g) : "memory");
}

// mma.sync m16n8k16 fp16 inputs, fp32 accumulate
__device__ __forceinline__ void mma_f16(float* c, const uint32_t* a, const uint32_t* b) {
    asm volatile(
        "mma.sync.aligned.m16n8k16.row.col.f32.f16.f16.f32 "
        "{%0,%1,%2,%3}, {%4,%5,%6,%7}, {%8,%9}, {%0,%1,%2,%3};"
        : "+f"(c[0]), "+f"(c[1]), "+f"(c[2]), "+f"(c[3])
        : "r"(a[0]), "r"(a[1]), "r"(a[2]), "r"(a[3]), "r"(b[0]), "r"(b[1]));
}

__device__ __forceinline__ void ldm4(uint32_t* r, uint32_t a) {
    asm volatile("ldmatrix.sync.aligned.m8n8.x4.shared.b16 {%0,%1,%2,%3}, [%4];"
                 : "=r"(r[0]), "=r"(r[1]), "=r"(r[2]), "=r"(r[3]) : "r"(a));
}

__device__ __forceinline__ void store2(float* p, float x, float y) {
    float2 t; t.x = x; t.y = y; *(float2*)p = t;
}
__device__ __forceinline__ void store2(__half* p, float x, float y) {
    *(__half2*)p = __floats2half2_rn(x, y);
}

// =================== mma.sync FP16 GEMM (round-9 proven config) =================
// 128x128 CTA tile, 128 threads (2x2 warps, 64x64 warp tile), BK=64 halfs,
// 3-stage cp.async pipeline, ldmatrix fragments double-buffered, 2 CTAs/SM.
enum { EPI_NONE = 0, EPI_SIGMOID = 1, EPI_GELU = 2, EPI_ADD = 3 };

#define TILE_B   16384                 // 128 rows * 128 bytes (64 halfs)
#define STAGE_B  (2 * TILE_B)
#define NSTG     3
#define GEMM_SMEM (NSTG * STAGE_B)     // 98304 bytes

template <int EPI, typename OutT>
__global__ __launch_bounds__(128, 2) void gemm_mma(
    const __half* __restrict__ A, const __half* __restrict__ Bt,
    const float* __restrict__ bias, const __half* __restrict__ addsrc,
    OutT* __restrict__ C, int M, int N, int K)
{
    extern __shared__ char smraw[];
    uint32_t smb = smem_u32(smraw);

    int tid  = threadIdx.x;
    int warp = tid >> 5, lane = tid & 31;
    int g = lane >> 2, t = lane & 3;
    int wm = warp >> 1, wn = warp & 1;          // 2 x 2 warp grid, 64x64 tiles
    int row0 = blockIdx.y * 128;
    int col0 = blockIdx.x * 128;
    int KCH  = K >> 6;                          // K chunks of 64 halfs (128B)

    // ---- gmem->smem load mapping: rows lr+16i, 16B chunk lc -------------------
    int lr = tid >> 3;          // 0..15
    int lc = tid & 7;           // 0..7
    uint32_t st_off[8];
    #pragma unroll
    for (int i = 0; i < 8; i++) {
        int row = lr + 16 * i;
        st_off[i] = (uint32_t)(row * 128 + ((lc ^ (row & 7)) << 4));
    }
    const __half* gA = A  + (size_t)(row0 + lr) * K + lc * 8;
    const __half* gB = Bt + (size_t)(col0 + lr) * K + lc * 8;

    // ---- ldmatrix per-lane address offsets (k-slice 0; advance via ^(ks<<5)) ---
    uint32_t rxor = (uint32_t)(lane & 7) << 4;
    uint32_t aoff[4], boff[4];
    #pragma unroll
    for (int i = 0; i < 4; i++) {
        int arow = wm * 64 + i * 16 + ((lane >> 3) & 1) * 8 + (lane & 7);
        aoff[i] = (uint32_t)arow * 128 + (((uint32_t)((lane >> 4) & 1) << 4) ^ rxor);
    }
    #pragma unroll
    for (int jp = 0; jp < 4; jp++) {
        int brow = wn * 64 + jp * 16 + (((lane >> 4) & 1) << 3) + (lane & 7);
        boff[jp] = (uint32_t)brow * 128 + (((uint32_t)((lane >> 3) & 1) << 4) ^ rxor);
    }

    float c[4][8][4];
    #pragma unroll
    for (int i = 0; i < 4; i++)
        #pragma unroll
        for (int j = 0; j < 8; j++)
            #pragma unroll
            for (int q = 0; q < 4; q++) c[i][j][q] = 0.f;

    // prologue: stages 0,1
    #pragma unroll
    for (int s = 0; s < 2; s++) {
        uint32_t ab = smb + s * STAGE_B;
        uint32_t bb = ab + TILE_B;
        #pragma unroll
        for (int i = 0; i < 8; i++) {
            cpasync16(ab + st_off[i], gA + (size_t)i * 16 * K + s * 64);
            cpasync16(bb + st_off[i], gB + (size_t)i * 16 * K + s * 64);
        }
        CP_COMMIT();
    }

    for (int kc = 0; kc < KCH; kc++) {
        cp_wait<1>();
        __syncthreads();

        if (kc + 2 < KCH) {
            int s2 = (kc + 2) % NSTG;
            uint32_t ab = smb + s2 * STAGE_B;
            uint32_t bb = ab + TILE_B;
            #pragma unroll
            for (int i = 0; i < 8; i++) {
                cpasync16(ab + st_off[i], gA + (size_t)i * 16 * K + (kc + 2) * 64);
                cpasync16(bb + st_off[i], gB + (size_t)i * 16 * K + (kc + 2) * 64);
            }
        }
        CP_COMMIT();

        uint32_t sAst = smb + (kc % NSTG) * STAGE_B;
        uint32_t sBst = sAst + TILE_B;

        uint32_t af[2][4][4], bf[2][4][4];
        #pragma unroll
        for (int i = 0; i < 4; i++) ldm4(af[0][i], sAst + aoff[i]);
        #pragma unroll
        for (int jp = 0; jp < 4; jp++) ldm4(bf[0][jp], sBst + boff[jp]);

        #pragma unroll
        for (int ks = 0; ks < 4; ks++) {
            int cb = ks & 1, nb = cb ^ 1;
            if (ks < 3) {
                uint32_t kx = (uint32_t)(ks + 1) << 5;
                #pragma unroll
                for (int i = 0; i < 4; i++) ldm4(af[nb][i], sAst + (aoff[i] ^ kx));
                #pragma unroll
                for (int jp = 0; jp < 4; jp++) ldm4(bf[nb][jp], sBst + (boff[jp] ^ kx));
            }
            #pragma unroll
            for (int i = 0; i < 4; i++)
                #pragma unroll
                for (int jp = 0; jp < 4; jp++) {
                    mma_f16(c[i][2 * jp],     af[cb][i], &bf[cb][jp][0]);
                    mma_f16(c[i][2 * jp + 1], af[cb][i], &bf[cb][jp][2]);
                }
        }
    }

    // ---- epilogue ---------------------------------------------------------------
    #pragma unroll
    for (int i = 0; i < 4; i++) {
        int rlo = row0 + wm * 64 + i * 16 + g;
        #pragma unroll
        for (int j = 0; j < 8; j++) {
            int col = col0 + wn * 64 + j * 8 + 2 * t;
            float2 bv = *(const float2*)(bias + col);
            float lox = c[i][j][0] + bv.x, loy = c[i][j][1] + bv.y;
            float hix = c[i][j][2] + bv.x, hiy = c[i][j][3] + bv.y;
            size_t olo = (size_t)rlo * N + col;
            size_t ohi = olo + (size_t)8 * N;
            if (EPI == EPI_SIGMOID) {
                lox = 1.f / (1.f + __expf(-lox)); loy = 1.f / (1.f + __expf(-loy));
                hix = 1.f / (1.f + __expf(-hix)); hiy = 1.f / (1.f + __expf(-hiy));
            } else if (EPI == EPI_GELU) {
                lox = 0.5f * lox * (1.f + erff(lox * 0.70710678118654752f));
                loy = 0.5f * loy * (1.f + erff(loy * 0.70710678118654752f));
                hix = 0.5f * hix * (1.f + erff(hix * 0.70710678118654752f));
                hiy = 0.5f * hiy * (1.f + erff(hiy * 0.70710678118654752f));
            } else if (EPI == EPI_ADD) {
                float2 a0 = __half22float2(*(const __half2*)(addsrc + olo));
                float2 a1 = __half22float2(*(const __half2*)(addsrc + ohi));
                lox += a0.x; loy += a0.y; hix += a1.x; hiy += a1.y;
            }
            store2(C + olo, lox, loy);
            store2(C + ohi, hix, hiy);
        }
    }
}

// =================== transpose (f32 -> f16): in[R,C] -> out[C,R] ===============
__global__ __launch_bounds__(256) void transpose_kernel(
    const float* __restrict__ in, __half* __restrict__ out, int R, int C)
{
    __shared__ float t[32][33];
    int bx = blockIdx.x * 32, by = blockIdx.y * 32;
    int tx = threadIdx.x & 31, ty = threadIdx.x >> 5;
    #pragma unroll
    for (int i = 0; i < 32; i += 8)
        t[ty + i][tx] = in[(size_t)(by + ty + i) * C + bx + tx];
    __syncthreads();
    #pragma unroll
    for (int i = 0; i < 32; i += 8)
        out[(size_t)(bx + ty + i) * R + by + tx] = __float2half_rn(t[tx][ty + i]);
}

// =================== LayerNorm (f32 in, f16 out) — used for LN1 ================
__global__ __launch_bounds__(256) void ln_kernel(
    const float* __restrict__ x, const float* __restrict__ gamma,
    const float* __restrict__ beta, __half* __restrict__ out)
{
    int row = blockIdx.x;
    int tid = threadIdx.x;
    const float4* xr = (const float4*)(x + (size_t)row * D_);
    float4 v = xr[tid];

    float s  = v.x + v.y + v.z + v.w;
    float sq = v.x*v.x + v.y*v.y + v.z*v.z + v.w*v.w;

    __shared__ float red0[8], red1[8];
    #pragma unroll
    for (int o = 16; o > 0; o >>= 1) {
        s  += __shfl_xor_sync(0xffffffffu, s,  o);
        sq += __shfl_xor_sync(0xffffffffu, sq, o);
    }
    if ((tid & 31) == 0) { red0[tid >> 5] = s; red1[tid >> 5] = sq; }
    __syncthreads();
    if (tid < 32) {
        s  = (tid < 8) ? red0[tid] : 0.f;
        sq = (tid < 8) ? red1[tid] : 0.f;
        #pragma unroll
        for (int o = 4; o > 0; o >>= 1) {
            s  += __shfl_xor_sync(0xffffffffu, s,  o);
            sq += __shfl_xor_sync(0xffffffffu, sq, o);
        }
        if (tid == 0) {
            float mu = s * (1.0f / D_);
            float var = sq * (1.0f / D_) - mu * mu;
            red0[0] = mu;
            red1[0] = rsqrtf(var + 1e-5f);
        }
    }
    __syncthreads();
    float mu = red0[0], rstd = red1[0];

    float4 gv = ((const float4*)gamma)[tid];
    float4 bv = ((const float4*)beta)[tid];
    __half2* orow = (__half2*)(out + (size_t)row * D_);
    orow[tid * 2]     = __floats2half2_rn((v.x - mu) * rstd * gv.x + bv.x,
                                          (v.y - mu) * rstd * gv.y + bv.y);
    orow[tid * 2 + 1] = __floats2half2_rn((v.z - mu) * rstd * gv.z + bv.z,
                                          (v.w - mu) * rstd * gv.w + bv.w);
}

// =================== cumsum passes (g, v in fp16) ==============================
__global__ __launch_bounds__(256) void cums_partial(
    const __half* __restrict__ g, const __half* __restrict__ v,
    float* __restrict__ pg, float* __restrict__ pgv)
{
    int bs  = blockIdx.x;            // b*NSEG + seg
    int b   = bs >> 7;
    int seg = bs & 127;
    int d   = (blockIdx.y * 256 + threadIdx.x) * 2;   // half2 lane
    size_t base = ((size_t)b * S_ + (size_t)seg * SEGLEN) * D_ + d;

    float2 sg = {0.f, 0.f}, sgv = {0.f, 0.f};
    #pragma unroll 4
    for (int s = 0; s < SEGLEN; s++) {
        float2 g2 = __half22float2(*(const __half2*)(g + base + (size_t)s * D_));
        float2 v2 = __half22float2(*(const __half2*)(v + base + (size_t)s * D_));
        sg.x  += g2.x;        sg.y  += g2.y;
        sgv.x += g2.x * v2.x; sgv.y += g2.y * v2.y;
    }
    size_t o = (size_t)bs * D_ + d;
    *(float2*)(pg  + o) = sg;
    *(float2*)(pgv + o) = sgv;
}

// Exclusive scan over NSEG segments per (b,d), batched loads for MLP.
__global__ __launch_bounds__(256) void cums_scan(
    float* __restrict__ pg, float* __restrict__ pgv)
{
    int idx = blockIdx.x * 256 + threadIdx.x;  // 0 .. B_*D_-1
    int b = idx / D_;
    int d = idx % D_;
    size_t base = (size_t)b * NSEG * D_ + d;
    float rg = 0.f, rgv = 0.f;
    float tg[8], tv[8];
    for (int s0 = 0; s0 < NSEG; s0 += 8) {
        #pragma unroll
        for (int k = 0; k < 8; k++) {
            size_t o = base + (size_t)(s0 + k) * D_;
            tg[k] = pg[o];
            tv[k] = pgv[o];
        }
        #pragma unroll
        for (int k = 0; k < 8; k++) {
            size_t o = base + (size_t)(s0 + k) * D_;
            pg[o]  = rg;
            pgv[o] = rgv;
            rg  += tg[k];
            rgv += tv[k];
        }
    }
}

// ---- fused: inclusive cumsum-apply + residual (f16 xn) + LayerNorm2 (f16 h2) --
__global__ __launch_bounds__(256) void cums_ln2(
    const __half* __restrict__ g, const __half* __restrict__ v,
    const float* __restrict__ x,
    const float* __restrict__ pg, const float* __restrict__ pgv,
    const float* __restrict__ gamma, const float* __restrict__ beta,
    __half* __restrict__ xout, __half* __restrict__ h2)
{
    int bs  = blockIdx.x;            // b*NSEG + seg
    int b   = bs >> 7;
    int seg = bs & 127;
    int tid = threadIdx.x;
    int wid = tid >> 5, lid = tid & 31;

    size_t rowbase = (size_t)b * S_ + (size_t)seg * SEGLEN;
    size_t po = (size_t)bs * D_ + tid * 4;
    float4 rg  = *(const float4*)(pg  + po);
    float4 rgv = *(const float4*)(pgv + po);
    float4 gm  = ((const float4*)gamma)[tid];
    float4 bt  = ((const float4*)beta)[tid];

    __shared__ float red0[8], red1[8], bmu[2];

    for (int s = 0; s < SEGLEN; s++) {
        size_t o = (rowbase + s) * D_ + tid * 4;
        float2 ga = __half22float2(*(const __half2*)(g + o));
        float2 gb = __half22float2(*(const __half2*)(g + o + 2));
        float2 va = __half22float2(*(const __half2*)(v + o));
        float2 vb = __half22float2(*(const __half2*)(v + o + 2));
        float4 x4 = *(const float4*)(x + o);

        rgv.x += ga.x * va.x;  rg.x += ga.x;
        rgv.y += ga.y * va.y;  rg.y += ga.y;
        rgv.z += gb.x * vb.x;  rg.z += gb.x;
        rgv.w += gb.y * vb.y;  rg.w += gb.y;

        float4 xo;
        xo.x = x4.x + rgv.x / (rg.x + 1e-6f);
        xo.y = x4.y + rgv.y / (rg.y + 1e-6f);
        xo.z = x4.z + rgv.z / (rg.z + 1e-6f);
        xo.w = x4.w + rgv.w / (rg.w + 1e-6f);
        __half2* xrow = (__half2*)(xout + o);
        xrow[0] = __floats2half2_rn(xo.x, xo.y);
        xrow[1] = __floats2half2_rn(xo.z, xo.w);

        float ss = xo.x + xo.y + xo.z + xo.w;
        float sq = xo.x*xo.x + xo.y*xo.y + xo.z*xo.z + xo.w*xo.w;
        #pragma unroll
        for (int of = 16; of > 0; of >>= 1) {
            ss += __shfl_xor_sync(0xffffffffu, ss, of);
            sq += __shfl_xor_sync(0xffffffffu, sq, of);
        }
        if (lid == 0) { red0[wid] = ss; red1[wid] = sq; }
        __syncthreads();
        if (tid < 32) {
            float a = (tid < 8) ? red0[tid] : 0.f;
            float q = (tid < 8) ? red1[tid] : 0.f;
            #pragma unroll
            for (int of = 4; of > 0; of >>= 1) {
                a += __shfl_xor_sync(0xffffffffu, a, of);
                q += __shfl_xor_sync(0xffffffffu, q, of);
            }
            if (tid == 0) {
                float mu = a * (1.0f / D_);
                float var = q * (1.0f / D_) - mu * mu;
                bmu[0] = mu;
                bmu[1] = rsqrtf(var + 1e-5f);
            }
        }
        __syncthreads();
        float mu = bmu[0], rstd = bmu[1];

        __half2* hrow = (__half2*)(h2 + (rowbase + s) * D_);
        hrow[tid * 2]     = __floats2half2_rn((xo.x - mu) * rstd * gm.x + bt.x,
                                              (xo.y - mu) * rstd * gm.y + bt.y);
        hrow[tid * 2 + 1] = __floats2half2_rn((xo.z - mu) * rstd * gm.z + bt.z,
                                              (xo.w - mu) * rstd * gm.w + bt.w);
    }
}

// =================== launch ====================================================
extern "C" void kernel_launch(void* const* d_in, const int* in_sizes, int n_in,
                              void* d_out, int out_size)
{
    const float* x       = (const float*)d_in[0];
    const float* ln1_g   = (const float*)d_in[1];
    const float* ln1_b   = (const float*)d_in[2];
    const float* ln2_g   = (const float*)d_in[3];
    const float* ln2_b   = (const float*)d_in[4];
    const float* gate_w  = (const float*)d_in[5];
    const float* gate_b  = (const float*)d_in[6];
    const float* value_w = (const float*)d_in[7];
    const float* value_b = (const float*)d_in[8];
    const float* ffn_w1  = (const float*)d_in[9];
    const float* ffn_b1  = (const float*)d_in[10];
    const float* ffn_w2  = (const float*)d_in[11];
    const float* ffn_b2  = (const float*)d_in[12];
    float* out = (float*)d_out;

    __half *h, *h2, *u, *gwt, *vwt, *w1t, *w2t, *g, *v, *xn;
    float *pg, *pgv;
    cudaGetSymbolAddress((void**)&h,   sc_h);
    cudaGetSymbolAddress((void**)&g,   sc_g);
    cudaGetSymbolAddress((void**)&v,   sc_v);
    cudaGetSymbolAddress((void**)&xn,  sc_x);
    cudaGetSymbolAddress((void**)&h2,  sc_h2);
    cudaGetSymbolAddress((void**)&u,   sc_u);
    cudaGetSymbolAddress((void**)&pg,  sc_pg);
    cudaGetSymbolAddress((void**)&pgv, sc_pgv);
    cudaGetSymbolAddress((void**)&gwt, sc_gwt);
    cudaGetSymbolAddress((void**)&vwt, sc_vwt);
    cudaGetSymbolAddress((void**)&w1t, sc_w1t);
    cudaGetSymbolAddress((void**)&w2t, sc_w2t);

    cudaFuncSetAttribute(gemm_mma<EPI_SIGMOID, __half>, cudaFuncAttributeMaxDynamicSharedMemorySize, GEMM_SMEM);
    cudaFuncSetAttribute(gemm_mma<EPI_NONE, __half>,    cudaFuncAttributeMaxDynamicSharedMemorySize, GEMM_SMEM);
    cudaFuncSetAttribute(gemm_mma<EPI_GELU, __half>,    cudaFuncAttributeMaxDynamicSharedMemorySize, GEMM_SMEM);
    cudaFuncSetAttribute(gemm_mma<EPI_ADD, float>,      cudaFuncAttributeMaxDynamicSharedMemorySize, GEMM_SMEM);

    // 0. transpose weights to [N,K] fp16
    transpose_kernel<<<dim3(D_/32, D_/32),   256>>>(gate_w,  gwt, D_, D_);
    transpose_kernel<<<dim3(D_/32, D_/32),   256>>>(value_w, vwt, D_, D_);
    transpose_kernel<<<dim3(4*D_/32, D_/32), 256>>>(ffn_w1,  w1t, D_, 4*D_);
    transpose_kernel<<<dim3(D_/32, 4*D_/32), 256>>>(ffn_w2,  w2t, 4*D_, D_);

    // 1. h = LN1(x)  (fp16)
    ln_kernel<<<ROWS, 256>>>(x, ln1_g, ln1_b, h);

    // 2/3. gate + value GEMMs (fp16 outputs)
    dim3 gridDD(D_ / 128, ROWS / 128);
    gemm_mma<EPI_SIGMOID, __half><<<gridDD, 128, GEMM_SMEM>>>(h, gwt, gate_b, nullptr, g, ROWS, D_, D_);
    gemm_mma<EPI_NONE, __half>   <<<gridDD, 128, GEMM_SMEM>>>(h, vwt, value_b, nullptr, v, ROWS, D_, D_);

    // 4. memory residual + LN2 (fused)
    cums_partial<<<dim3(B_ * NSEG, D_ / 512), 256>>>(g, v, pg, pgv);
    cums_scan<<<(B_ * D_) / 256, 256>>>(pg, pgv);
    cums_ln2<<<B_ * NSEG, 256>>>(g, v, x, pg, pgv, ln2_g, ln2_b, xn, h2);

    // 6. u = gelu(h2 @ W1 + b1)  (fp16 out)
    dim3 gridFF1(4 * D_ / 128, ROWS / 128);
    gemm_mma<EPI_GELU, __half><<<gridFF1, 128, GEMM_SMEM>>>(h2, w1t, ffn_b1, nullptr, u, ROWS, 4 * D_, D_);

    // 7. out = x_new + u @ W2 + b2
    gemm_mma<EPI_ADD, float><<<gridDD, 128, GEMM_SMEM>>>(u, w2t, ffn_b2, xn, out, ROWS, D_, 4 * D_);
}

// round 12
// speedup vs baseline: 1.1772x; 1.0133x over previous
#include <cuda_runtime.h>
#include <cuda_fp16.h>
#include <math.h>
#include <stdint.h>

#define B_   4
#define S_   4096
#define D_   1024
#define ROWS (B_ * S_)        // 16384
#define NSEG 128
#define SEGLEN (S_ / NSEG)    // 32
#define GVS  (2 * D_)         // stride of combined gate|value buffer

// ---------------- scratch (static device globals; no allocations) -------------
__device__ __half sc_h [(size_t)ROWS * D_];      // LN1 output (fp16)
__device__ __half sc_gv[(size_t)ROWS * GVS];     // [g | v] combined (fp16)
__device__ __half sc_x [(size_t)ROWS * D_];      // x after memory residual (fp16)
__device__ __half sc_h2[(size_t)ROWS * D_];      // LN2 output (fp16)
__device__ __half sc_u [(size_t)ROWS * 4 * D_];  // gelu out (fp16)
__device__ float  sc_pg [(size_t)B_ * NSEG * D_];
__device__ float  sc_pgv[(size_t)B_ * NSEG * D_];
__device__ __half sc_gvwt[(size_t)2 * D_ * D_];  // [gate_w^T ; value_w^T]  [2D,K]
__device__ __half sc_w1t[(size_t)4 * D_ * D_];   // ffn_w1^T  fp16
__device__ __half sc_w2t[(size_t)D_ * 4 * D_];   // ffn_w2^T  fp16

// =================== helpers ====================================================
__device__ __forceinline__ uint32_t smem_u32(const void* p) {
    uint32_t a;
    asm("{ .reg .u64 t; cvta.to.shared.u64 t, %1; cvt.u32.u64 %0, t; }"
        : "=r"(a) : "l"(p));
    return a;
}

#define CP_COMMIT() asm volatile("cp.async.commit_group;" ::: "memory")
template <int N> __device__ __forceinline__ void cp_wait() {
    asm volatile("cp.async.wait_group %0;" :: "n"(N) : "memory");
}
__device__ __forceinline__ void cpasync16(uint32_t saddr, const void* g) {
    asm volatile("cp.async.cg.shared.global [%0], [%1], 16;"
                 :: "r"(saddr), "l"(g) : "memory");
}

// mma.sync m16n8k16 fp16 inputs, fp32 accumulate
__device__ __forceinline__ void mma_f16(float* c, const uint32_t* a, const uint32_t* b) {
    asm volatile(
        "mma.sync.aligned.m16n8k16.row.col.f32.f16.f16.f32 "
        "{%0,%1,%2,%3}, {%4,%5,%6,%7}, {%8,%9}, {%0,%1,%2,%3};"
        : "+f"(c[0]), "+f"(c[1]), "+f"(c[2]), "+f"(c[3])
        : "r"(a[0]), "r"(a[1]), "r"(a[2]), "r"(a[3]), "r"(b[0]), "r"(b[1]));
}

__device__ __forceinline__ void ldm4(uint32_t* r, uint32_t a) {
    asm volatile("ldmatrix.sync.aligned.m8n8.x4.shared.b16 {%0,%1,%2,%3}, [%4];"
                 : "=r"(r[0]), "=r"(r[1]), "=r"(r[2]), "=r"(r[3]) : "r"(a));
}

__device__ __forceinline__ void store2(float* p, float x, float y) {
    float2 t; t.x = x; t.y = y; *(float2*)p = t;
}
__device__ __forceinline__ void store2(__half* p, float x, float y) {
    *(__half2*)p = __floats2half2_rn(x, y);
}

// =================== mma.sync FP16 GEMM (round-9 proven config) =================
// 128x128 CTA tile, 128 threads (2x2 warps, 64x64 warp tile), BK=64 halfs,
// 3-stage cp.async pipeline, ldmatrix fragments double-buffered, 2 CTAs/SM.
// EPI_GV: sigmoid iff CTA's col block < D_ (gate half); bias2 for value half.
enum { EPI_NONE = 0, EPI_SIGMOID = 1, EPI_GELU = 2, EPI_ADD = 3, EPI_GV = 4 };

#define TILE_B   16384                 // 128 rows * 128 bytes (64 halfs)
#define STAGE_B  (2 * TILE_B)
#define NSTG     3
#define GEMM_SMEM (NSTG * STAGE_B)     // 98304 bytes

template <int EPI, typename OutT>
__global__ __launch_bounds__(128, 2) void gemm_mma(
    const __half* __restrict__ A, const __half* __restrict__ Bt,
    const float* __restrict__ bias, const float* __restrict__ bias2,
    const __half* __restrict__ addsrc,
    OutT* __restrict__ C, int M, int N, int K)
{
    extern __shared__ char smraw[];
    uint32_t smb = smem_u32(smraw);

    int tid  = threadIdx.x;
    int warp = tid >> 5, lane = tid & 31;
    int g = lane >> 2, t = lane & 3;
    int wm = warp >> 1, wn = warp & 1;          // 2 x 2 warp grid, 64x64 tiles
    int row0 = blockIdx.y * 128;
    int col0 = blockIdx.x * 128;
    int KCH  = K >> 6;                          // K chunks of 64 halfs (128B)

    // ---- gmem->smem load mapping: rows lr+16i, 16B chunk lc -------------------
    int lr = tid >> 3;          // 0..15
    int lc = tid & 7;           // 0..7
    uint32_t st_off[8];
    #pragma unroll
    for (int i = 0; i < 8; i++) {
        int row = lr + 16 * i;
        st_off[i] = (uint32_t)(row * 128 + ((lc ^ (row & 7)) << 4));
    }
    const __half* gA = A  + (size_t)(row0 + lr) * K + lc * 8;
    const __half* gB = Bt + (size_t)(col0 + lr) * K + lc * 8;

    // ---- ldmatrix per-lane address offsets (k-slice 0; advance via ^(ks<<5)) ---
    uint32_t rxor = (uint32_t)(lane & 7) << 4;
    uint32_t aoff[4], boff[4];
    #pragma unroll
    for (int i = 0; i < 4; i++) {
        int arow = wm * 64 + i * 16 + ((lane >> 3) & 1) * 8 + (lane & 7);
        aoff[i] = (uint32_t)arow * 128 + (((uint32_t)((lane >> 4) & 1) << 4) ^ rxor);
    }
    #pragma unroll
    for (int jp = 0; jp < 4; jp++) {
        int brow = wn * 64 + jp * 16 + (((lane >> 4) & 1) << 3) + (lane & 7);
        boff[jp] = (uint32_t)brow * 128 + (((uint32_t)((lane >> 3) & 1) << 4) ^ rxor);
    }

    float c[4][8][4];
    #pragma unroll
    for (int i = 0; i < 4; i++)
        #pragma unroll
        for (int j = 0; j < 8; j++)
            #pragma unroll
            for (int q = 0; q < 4; q++) c[i][j][q] = 0.f;

    // prologue: stages 0,1
    #pragma unroll
    for (int s = 0; s < 2; s++) {
        uint32_t ab = smb + s * STAGE_B;
        uint32_t bb = ab + TILE_B;
        #pragma unroll
        for (int i = 0; i < 8; i++) {
            cpasync16(ab + st_off[i], gA + (size_t)i * 16 * K + s * 64);
            cpasync16(bb + st_off[i], gB + (size_t)i * 16 * K + s * 64);
        }
        CP_COMMIT();
    }

    for (int kc = 0; kc < KCH; kc++) {
        cp_wait<1>();
        __syncthreads();

        if (kc + 2 < KCH) {
            int s2 = (kc + 2) % NSTG;
            uint32_t ab = smb + s2 * STAGE_B;
            uint32_t bb = ab + TILE_B;
            #pragma unroll
            for (int i = 0; i < 8; i++) {
                cpasync16(ab + st_off[i], gA + (size_t)i * 16 * K + (kc + 2) * 64);
                cpasync16(bb + st_off[i], gB + (size_t)i * 16 * K + (kc + 2) * 64);
            }
        }
        CP_COMMIT();

        uint32_t sAst = smb + (kc % NSTG) * STAGE_B;
        uint32_t sBst = sAst + TILE_B;

        uint32_t af[2][4][4], bf[2][4][4];
        #pragma unroll
        for (int i = 0; i < 4; i++) ldm4(af[0][i], sAst + aoff[i]);
        #pragma unroll
        for (int jp = 0; jp < 4; jp++) ldm4(bf[0][jp], sBst + boff[jp]);

        #pragma unroll
        for (int ks = 0; ks < 4; ks++) {
            int cb = ks & 1, nb = cb ^ 1;
            if (ks < 3) {
                uint32_t kx = (uint32_t)(ks + 1) << 5;
                #pragma unroll
                for (int i = 0; i < 4; i++) ldm4(af[nb][i], sAst + (aoff[i] ^ kx));
                #pragma unroll
                for (int jp = 0; jp < 4; jp++) ldm4(bf[nb][jp], sBst + (boff[jp] ^ kx));
            }
            #pragma unroll
            for (int i = 0; i < 4; i++)
                #pragma unroll
                for (int jp = 0; jp < 4; jp++) {
                    mma_f16(c[i][2 * jp],     af[cb][i], &bf[cb][jp][0]);
                    mma_f16(c[i][2 * jp + 1], af[cb][i], &bf[cb][jp][2]);
                }
        }
    }

    // ---- epilogue ---------------------------------------------------------------
    // EPI_GV: whole CTA is in gate half (sigmoid) or value half (plain), uniform.
    const float* bp = bias;
    int coff = 0;
    bool gv_sig = true;
    if (EPI == EPI_GV && col0 >= D_) { bp = bias2; coff = D_; gv_sig = false; }

    #pragma unroll
    for (int i = 0; i < 4; i++) {
        int rlo = row0 + wm * 64 + i * 16 + g;
        #pragma unroll
        for (int j = 0; j < 8; j++) {
            int col = col0 + wn * 64 + j * 8 + 2 * t;
            float2 bv = *(const float2*)(bp + col - coff);
            float lox = c[i][j][0] + bv.x, loy = c[i][j][1] + bv.y;
            float hix = c[i][j][2] + bv.x, hiy = c[i][j][3] + bv.y;
            size_t olo = (size_t)rlo * N + col;
            size_t ohi = olo + (size_t)8 * N;
            if (EPI == EPI_SIGMOID || (EPI == EPI_GV && gv_sig)) {
                lox = 1.f / (1.f + __expf(-lox)); loy = 1.f / (1.f + __expf(-loy));
                hix = 1.f / (1.f + __expf(-hix)); hiy = 1.f / (1.f + __expf(-hiy));
            } else if (EPI == EPI_GELU) {
                lox = 0.5f * lox * (1.f + erff(lox * 0.70710678118654752f));
                loy = 0.5f * loy * (1.f + erff(loy * 0.70710678118654752f));
                hix = 0.5f * hix * (1.f + erff(hix * 0.70710678118654752f));
                hiy = 0.5f * hiy * (1.f + erff(hiy * 0.70710678118654752f));
            } else if (EPI == EPI_ADD) {
                float2 a0 = __half22float2(*(const __half2*)(addsrc + olo));
                float2 a1 = __half22float2(*(const __half2*)(addsrc + ohi));
                lox += a0.x; loy += a0.y; hix += a1.x; hiy += a1.y;
            }
            store2(C + olo, lox, loy);
            store2(C + ohi, hix, hiy);
        }
    }
}

// =================== transpose (f32 -> f16): in[R,C] -> out[C,R] ===============
__global__ __launch_bounds__(256) void transpose_kernel(
    const float* __restrict__ in, __half* __restrict__ out, int R, int C)
{
    __shared__ float t[32][33];
    int bx = blockIdx.x * 32, by = blockIdx.y * 32;
    int tx = threadIdx.x & 31, ty = threadIdx.x >> 5;
    #pragma unroll
    for (int i = 0; i < 32; i += 8)
        t[ty + i][tx] = in[(size_t)(by + ty + i) * C + bx + tx];
    __syncthreads();
    #pragma unroll
    for (int i = 0; i < 32; i += 8)
        out[(size_t)(bx + ty + i) * R + by + tx] = __float2half_rn(t[tx][ty + i]);
}

// =================== LayerNorm (f32 in, f16 out) — used for LN1 ================
__global__ __launch_bounds__(256) void ln_kernel(
    const float* __restrict__ x, const float* __restrict__ gamma,
    const float* __restrict__ beta, __half* __restrict__ out)
{
    int row = blockIdx.x;
    int tid = threadIdx.x;
    const float4* xr = (const float4*)(x + (size_t)row * D_);
    float4 v = xr[tid];

    float s  = v.x + v.y + v.z + v.w;
    float sq = v.x*v.x + v.y*v.y + v.z*v.z + v.w*v.w;

    __shared__ float red0[8], red1[8];
    #pragma unroll
    for (int o = 16; o > 0; o >>= 1) {
        s  += __shfl_xor_sync(0xffffffffu, s,  o);
        sq += __shfl_xor_sync(0xffffffffu, sq, o);
    }
    if ((tid & 31) == 0) { red0[tid >> 5] = s; red1[tid >> 5] = sq; }
    __syncthreads();
    float a = 0.f, q = 0.f;
    #pragma unroll
    for (int w = 0; w < 8; w++) { a += red0[w]; q += red1[w]; }
    float mu = a * (1.0f / D_);
    float var = q * (1.0f / D_) - mu * mu;
    float rstd = rsqrtf(var + 1e-5f);

    float4 gv = ((const float4*)gamma)[tid];
    float4 bv = ((const float4*)beta)[tid];
    __half2* orow = (__half2*)(out + (size_t)row * D_);
    orow[tid * 2]     = __floats2half2_rn((v.x - mu) * rstd * gv.x + bv.x,
                                          (v.y - mu) * rstd * gv.y + bv.y);
    orow[tid * 2 + 1] = __floats2half2_rn((v.z - mu) * rstd * gv.z + bv.z,
                                          (v.w - mu) * rstd * gv.w + bv.w);
}

// =================== cumsum passes (g, v packed in gv[ROWS, 2D]) ===============
__global__ __launch_bounds__(256) void cums_partial(
    const __half* __restrict__ gv,
    float* __restrict__ pg, float* __restrict__ pgv)
{
    int bs  = blockIdx.x;            // b*NSEG + seg
    int b   = bs >> 7;
    int seg = bs & 127;
    int d   = (blockIdx.y * 256 + threadIdx.x) * 2;   // half2 lane
    size_t base = ((size_t)b * S_ + (size_t)seg * SEGLEN) * GVS + d;

    float2 sg = {0.f, 0.f}, sgv = {0.f, 0.f};
    #pragma unroll 4
    for (int s = 0; s < SEGLEN; s++) {
        float2 g2 = __half22float2(*(const __half2*)(gv + base + (size_t)s * GVS));
        float2 v2 = __half22float2(*(const __half2*)(gv + base + (size_t)s * GVS + D_));
        sg.x  += g2.x;        sg.y  += g2.y;
        sgv.x += g2.x * v2.x; sgv.y += g2.y * v2.y;
    }
    size_t o = (size_t)bs * D_ + d;
    *(float2*)(pg  + o) = sg;
    *(float2*)(pgv + o) = sgv;
}

// Exclusive scan over NSEG segments per (b,d), batched loads for MLP.
__global__ __launch_bounds__(256) void cums_scan(
    float* __restrict__ pg, float* __restrict__ pgv)
{
    int idx = blockIdx.x * 256 + threadIdx.x;  // 0 .. B_*D_-1
    int b = idx / D_;
    int d = idx % D_;
    size_t base = (size_t)b * NSEG * D_ + d;
    float rg = 0.f, rgv = 0.f;
    float tg[8], tv[8];
    for (int s0 = 0; s0 < NSEG; s0 += 8) {
        #pragma unroll
        for (int k = 0; k < 8; k++) {
            size_t o = base + (size_t)(s0 + k) * D_;
            tg[k] = pg[o];
            tv[k] = pgv[o];
        }
        #pragma unroll
        for (int k = 0; k < 8; k++) {
            size_t o = base + (size_t)(s0 + k) * D_;
            pg[o]  = rg;
            pgv[o] = rgv;
            rg  += tg[k];
            rgv += tv[k];
        }
    }
}

// ---- fused: inclusive cumsum-apply + residual (f16 xn) + LayerNorm2 (f16 h2) --
// One __syncthreads per row; partial buffers double-buffered by row parity.
__global__ __launch_bounds__(256) void cums_ln2(
    const __half* __restrict__ gv,
    const float* __restrict__ x,
    const float* __restrict__ pg, const float* __restrict__ pgv,
    const float* __restrict__ gamma, const float* __restrict__ beta,
    __half* __restrict__ xout, __half* __restrict__ h2)
{
    int bs  = blockIdx.x;            // b*NSEG + seg
    int b   = bs >> 7;
    int seg = bs & 127;
    int tid = threadIdx.x;
    int wid = tid >> 5, lid = tid & 31;

    size_t rowbase = (size_t)b * S_ + (size_t)seg * SEGLEN;
    size_t po = (size_t)bs * D_ + tid * 4;
    float4 rg  = *(const float4*)(pg  + po);
    float4 rgv = *(const float4*)(pgv + po);
    float4 gm  = ((const float4*)gamma)[tid];
    float4 bt  = ((const float4*)beta)[tid];

    __shared__ float red0[2][8], red1[2][8];

    for (int s = 0; s < SEGLEN; s++) {
        size_t o  = (rowbase + s) * GVS + tid * 4;
        size_t od = (rowbase + s) * D_  + tid * 4;
        float2 ga = __half22float2(*(const __half2*)(gv + o));
        float2 gb = __half22float2(*(const __half2*)(gv + o + 2));
        float2 va = __half22float2(*(const __half2*)(gv + o + D_));
        float2 vb = __half22float2(*(const __half2*)(gv + o + D_ + 2));
        float4 x4 = *(const float4*)(x + od);

        rgv.x += ga.x * va.x;  rg.x += ga.x;
        rgv.y += ga.y * va.y;  rg.y += ga.y;
        rgv.z += gb.x * vb.x;  rg.z += gb.x;
        rgv.w += gb.y * vb.y;  rg.w += gb.y;

        float4 xo;
        xo.x = x4.x + rgv.x / (rg.x + 1e-6f);
        xo.y = x4.y + rgv.y / (rg.y + 1e-6f);
        xo.z = x4.z + rgv.z / (rg.z + 1e-6f);
        xo.w = x4.w + rgv.w / (rg.w + 1e-6f);
        __half2* xrow = (__half2*)(xout + od);
        xrow[0] = __floats2half2_rn(xo.x, xo.y);
        xrow[1] = __floats2half2_rn(xo.z, xo.w);

        float ss = xo.x + xo.y + xo.z + xo.w;
        float sq = xo.x*xo.x + xo.y*xo.y + xo.z*xo.z + xo.w*xo.w;
        #pragma unroll
        for (int of = 16; of > 0; of >>= 1) {
            ss += __shfl_xor_sync(0xffffffffu, ss, of);
            sq += __shfl_xor_sync(0xffffffffu, sq, of);
        }
        int pb = s & 1;
        if (lid == 0) { red0[pb][wid] = ss; red1[pb][wid] = sq; }
        __syncthreads();
        float a = 0.f, q = 0.f;
        #pragma unroll
        for (int w = 0; w < 8; w++) { a += red0[pb][w]; q += red1[pb][w]; }
        float mu = a * (1.0f / D_);
        float var = q * (1.0f / D_) - mu * mu;
        float rstd = rsqrtf(var + 1e-5f);

        __half2* hrow = (__half2*)(h2 + od);
        hrow[0] = __floats2half2_rn((xo.x - mu) * rstd * gm.x + bt.x,
                                    (xo.y - mu) * rstd * gm.y + bt.y);
        hrow[1] = __floats2half2_rn((xo.z - mu) * rstd * gm.z + bt.z,
                                    (xo.w - mu) * rstd * gm.w + bt.w);
    }
}

// =================== launch ====================================================
extern "C" void kernel_launch(void* const* d_in, const int* in_sizes, int n_in,
                              void* d_out, int out_size)
{
    const float* x       = (const float*)d_in[0];
    const float* ln1_g   = (const float*)d_in[1];
    const float* ln1_b   = (const float*)d_in[2];
    const float* ln2_g   = (const float*)d_in[3];
    const float* ln2_b   = (const float*)d_in[4];
    const float* gate_w  = (const float*)d_in[5];
    const float* gate_b  = (const float*)d_in[6];
    const float* value_w = (const float*)d_in[7];
    const float* value_b = (const float*)d_in[8];
    const float* ffn_w1  = (const float*)d_in[9];
    const float* ffn_b1  = (const float*)d_in[10];
    const float* ffn_w2  = (const float*)d_in[11];
    const float* ffn_b2  = (const float*)d_in[12];
    float* out = (float*)d_out;

    __half *h, *h2, *u, *gvwt, *w1t, *w2t, *gv, *xn;
    float *pg, *pgv;
    cudaGetSymbolAddress((void**)&h,    sc_h);
    cudaGetSymbolAddress((void**)&gv,   sc_gv);
    cudaGetSymbolAddress((void**)&xn,   sc_x);
    cudaGetSymbolAddress((void**)&h2,   sc_h2);
    cudaGetSymbolAddress((void**)&u,    sc_u);
    cudaGetSymbolAddress((void**)&pg,   sc_pg);
    cudaGetSymbolAddress((void**)&pgv,  sc_pgv);
    cudaGetSymbolAddress((void**)&gvwt, sc_gvwt);
    cudaGetSymbolAddress((void**)&w1t,  sc_w1t);
    cudaGetSymbolAddress((void**)&w2t,  sc_w2t);

    cudaFuncSetAttribute(gemm_mma<EPI_GV, __half>,   cudaFuncAttributeMaxDynamicSharedMemorySize, GEMM_SMEM);
    cudaFuncSetAttribute(gemm_mma<EPI_GELU, __half>, cudaFuncAttributeMaxDynamicSharedMemorySize, GEMM_SMEM);
    cudaFuncSetAttribute(gemm_mma<EPI_ADD, float>,   cudaFuncAttributeMaxDynamicSharedMemorySize, GEMM_SMEM);

    // 0. transpose weights to [N,K] fp16; gate+value concatenated to [2D, K]
    transpose_kernel<<<dim3(D_/32, D_/32),   256>>>(gate_w,  gvwt, D_, D_);
    transpose_kernel<<<dim3(D_/32, D_/32),   256>>>(value_w, gvwt + (size_t)D_ * D_, D_, D_);
    transpose_kernel<<<dim3(4*D_/32, D_/32), 256>>>(ffn_w1,  w1t, D_, 4*D_);
    transpose_kernel<<<dim3(D_/32, 4*D_/32), 256>>>(ffn_w2,  w2t, 4*D_, D_);

    // 1. h = LN1(x)  (fp16)
    ln_kernel<<<ROWS, 256>>>(x, ln1_g, ln1_b, h);

    // 2. fused gate|value GEMM -> gv[ROWS, 2D]
    dim3 gridGV(GVS / 128, ROWS / 128);
    gemm_mma<EPI_GV, __half><<<gridGV, 128, GEMM_SMEM>>>(
        h, gvwt, gate_b, value_b, nullptr, gv, ROWS, GVS, D_);

    // 4. memory residual + LN2 (fused)
    cums_partial<<<dim3(B_ * NSEG, D_ / 512), 256>>>(gv, pg, pgv);
    cums_scan<<<(B_ * D_) / 256, 256>>>(pg, pgv);
    cums_ln2<<<B_ * NSEG, 256>>>(gv, x, pg, pgv, ln2_g, ln2_b, xn, h2);

    // 6. u = gelu(h2 @ W1 + b1)  (fp16 out)
    dim3 gridFF1(4 * D_ / 128, ROWS / 128);
    gemm_mma<EPI_GELU, __half><<<gridFF1, 128, GEMM_SMEM>>>(
        h2, w1t, ffn_b1, nullptr, nullptr, u, ROWS, 4 * D_, D_);

    // 7. out = x_new + u @ W2 + b2
    dim3 gridFF2(D_ / 128, ROWS / 128);
    gemm_mma<EPI_ADD, float><<<gridFF2, 128, GEMM_SMEM>>>(
        u, w2t, ffn_b2, nullptr, xn, out, ROWS, D_, 4 * D_);
}

// round 13
// speedup vs baseline: 1.1810x; 1.0032x over previous
#include <cuda_runtime.h>
#include <cuda_fp16.h>
#include <math.h>
#include <stdint.h>

#define B_   4
#define S_   4096
#define D_   1024
#define ROWS (B_ * S_)        // 16384
#define NSEG 128
#define SEGLEN (S_ / NSEG)    // 32
#define GVS  (2 * D_)         // stride of combined gate|value buffer

// ---------------- scratch (static device globals; no allocations) -------------
__device__ __half sc_h [(size_t)ROWS * D_];      // LN1 output (fp16)
__device__ __half sc_gv[(size_t)ROWS * GVS];     // [g | v] combined (fp16)
__device__ __half sc_x [(size_t)ROWS * D_];      // x after memory residual (fp16)
__device__ __half sc_h2[(size_t)ROWS * D_];      // LN2 output (fp16)
__device__ __half sc_u [(size_t)ROWS * 4 * D_];  // gelu out (fp16)
__device__ float  sc_pg [(size_t)B_ * NSEG * D_];
__device__ float  sc_pgv[(size_t)B_ * NSEG * D_];
__device__ __half sc_gvwt[(size_t)2 * D_ * D_];  // [gate_w^T ; value_w^T]  [2D,K]
__device__ __half sc_w1t[(size_t)4 * D_ * D_];   // ffn_w1^T  fp16
__device__ __half sc_w2t[(size_t)D_ * 4 * D_];   // ffn_w2^T  fp16

// =================== helpers ====================================================
__device__ __forceinline__ uint32_t smem_u32(const void* p) {
    uint32_t a;
    asm("{ .reg .u64 t; cvta.to.shared.u64 t, %1; cvt.u32.u64 %0, t; }"
        : "=r"(a) : "l"(p));
    return a;
}

#define CP_COMMIT() asm volatile("cp.async.commit_group;" ::: "memory")
template <int N> __device__ __forceinline__ void cp_wait() {
    asm volatile("cp.async.wait_group %0;" :: "n"(N) : "memory");
}
__device__ __forceinline__ void cpasync16(uint32_t saddr, const void* g) {
    asm volatile("cp.async.cg.shared.global [%0], [%1], 16;"
                 :: "r"(saddr), "l"(g) : "memory");
}

// mma.sync m16n8k16 fp16 inputs, fp32 accumulate
__device__ __forceinline__ void mma_f16(float* c, const uint32_t* a, const uint32_t* b) {
    asm volatile(
        "mma.sync.aligned.m16n8k16.row.col.f32.f16.f16.f32 "
        "{%0,%1,%2,%3}, {%4,%5,%6,%7}, {%8,%9}, {%0,%1,%2,%3};"
        : "+f"(c[0]), "+f"(c[1]), "+f"(c[2]), "+f"(c[3])
        : "r"(a[0]), "r"(a[1]), "r"(a[2]), "r"(a[3]), "r"(b[0]), "r"(b[1]));
}

__device__ __forceinline__ void ldm4(uint32_t* r, uint32_t a) {
    asm volatile("ldmatrix.sync.aligned.m8n8.x4.shared.b16 {%0,%1,%2,%3}, [%4];"
                 : "=r"(r[0]), "=r"(r[1]), "=r"(r[2]), "=r"(r[3]) : "r"(a));
}

__device__ __forceinline__ void store2(float* p, float x, float y) {
    float2 t; t.x = x; t.y = y; *(float2*)p = t;
}
__device__ __forceinline__ void store2(__half* p, float x, float y) {
    *(__half2*)p = __floats2half2_rn(x, y);
}

// =================== mma.sync FP16 GEMM (round-9 proven config) =================
// 128x128 CTA tile, 128 threads (2x2 warps, 64x64 warp tile), BK=64 halfs,
// 3-stage cp.async pipeline, ldmatrix fragments double-buffered, 2 CTAs/SM.
enum { EPI_NONE = 0, EPI_SIGMOID = 1, EPI_GELU = 2, EPI_ADD = 3, EPI_GV = 4 };

#define TILE_B   16384                 // 128 rows * 128 bytes (64 halfs)
#define STAGE_B  (2 * TILE_B)
#define NSTG     3
#define GEMM_SMEM (NSTG * STAGE_B)     // 98304 bytes

template <int EPI, typename OutT>
__global__ __launch_bounds__(128, 2) void gemm_mma(
    const __half* __restrict__ A, const __half* __restrict__ Bt,
    const float* __restrict__ bias, const float* __restrict__ bias2,
    const __half* __restrict__ addsrc,
    OutT* __restrict__ C, int M, int N, int K)
{
    extern __shared__ char smraw[];
    uint32_t smb = smem_u32(smraw);

    int tid  = threadIdx.x;
    int warp = tid >> 5, lane = tid & 31;
    int g = lane >> 2, t = lane & 3;
    int wm = warp >> 1, wn = warp & 1;          // 2 x 2 warp grid, 64x64 tiles
    int row0 = blockIdx.y * 128;
    int col0 = blockIdx.x * 128;
    int KCH  = K >> 6;                          // K chunks of 64 halfs (128B)

    // ---- gmem->smem load mapping: rows lr+16i, 16B chunk lc -------------------
    int lr = tid >> 3;          // 0..15
    int lc = tid & 7;           // 0..7
    uint32_t st_off[8];
    #pragma unroll
    for (int i = 0; i < 8; i++) {
        int row = lr + 16 * i;
        st_off[i] = (uint32_t)(row * 128 + ((lc ^ (row & 7)) << 4));
    }
    const __half* gA = A  + (size_t)(row0 + lr) * K + lc * 8;
    const __half* gB = Bt + (size_t)(col0 + lr) * K + lc * 8;

    // ---- ldmatrix per-lane address offsets (k-slice 0; advance via ^(ks<<5)) ---
    uint32_t rxor = (uint32_t)(lane & 7) << 4;
    uint32_t aoff[4], boff[4];
    #pragma unroll
    for (int i = 0; i < 4; i++) {
        int arow = wm * 64 + i * 16 + ((lane >> 3) & 1) * 8 + (lane & 7);
        aoff[i] = (uint32_t)arow * 128 + (((uint32_t)((lane >> 4) & 1) << 4) ^ rxor);
    }
    #pragma unroll
    for (int jp = 0; jp < 4; jp++) {
        int brow = wn * 64 + jp * 16 + (((lane >> 4) & 1) << 3) + (lane & 7);
        boff[jp] = (uint32_t)brow * 128 + (((uint32_t)((lane >> 3) & 1) << 4) ^ rxor);
    }

    float c[4][8][4];
    #pragma unroll
    for (int i = 0; i < 4; i++)
        #pragma unroll
        for (int j = 0; j < 8; j++)
            #pragma unroll
            for (int q = 0; q < 4; q++) c[i][j][q] = 0.f;

    // prologue: stages 0,1
    #pragma unroll
    for (int s = 0; s < 2; s++) {
        uint32_t ab = smb + s * STAGE_B;
        uint32_t bb = ab + TILE_B;
        #pragma unroll
        for (int i = 0; i < 8; i++) {
            cpasync16(ab + st_off[i], gA + (size_t)i * 16 * K + s * 64);
            cpasync16(bb + st_off[i], gB + (size_t)i * 16 * K + s * 64);
        }
        CP_COMMIT();
    }

    for (int kc = 0; kc < KCH; kc++) {
        cp_wait<1>();
        __syncthreads();

        if (kc + 2 < KCH) {
            int s2 = (kc + 2) % NSTG;
            uint32_t ab = smb + s2 * STAGE_B;
            uint32_t bb = ab + TILE_B;
            #pragma unroll
            for (int i = 0; i < 8; i++) {
                cpasync16(ab + st_off[i], gA + (size_t)i * 16 * K + (kc + 2) * 64);
                cpasync16(bb + st_off[i], gB + (size_t)i * 16 * K + (kc + 2) * 64);
            }
        }
        CP_COMMIT();

        uint32_t sAst = smb + (kc % NSTG) * STAGE_B;
        uint32_t sBst = sAst + TILE_B;

        uint32_t af[2][4][4], bf[2][4][4];
        #pragma unroll
        for (int i = 0; i < 4; i++) ldm4(af[0][i], sAst + aoff[i]);
        #pragma unroll
        for (int jp = 0; jp < 4; jp++) ldm4(bf[0][jp], sBst + boff[jp]);

        #pragma unroll
        for (int ks = 0; ks < 4; ks++) {
            int cb = ks & 1, nb = cb ^ 1;
            if (ks < 3) {
                uint32_t kx = (uint32_t)(ks + 1) << 5;
                #pragma unroll
                for (int i = 0; i < 4; i++) ldm4(af[nb][i], sAst + (aoff[i] ^ kx));
                #pragma unroll
                for (int jp = 0; jp < 4; jp++) ldm4(bf[nb][jp], sBst + (boff[jp] ^ kx));
            }
            #pragma unroll
            for (int i = 0; i < 4; i++)
                #pragma unroll
                for (int jp = 0; jp < 4; jp++) {
                    mma_f16(c[i][2 * jp],     af[cb][i], &bf[cb][jp][0]);
                    mma_f16(c[i][2 * jp + 1], af[cb][i], &bf[cb][jp][2]);
                }
        }
    }

    // ---- epilogue ---------------------------------------------------------------
    const float* bp = bias;
    int coff = 0;
    bool gv_sig = true;
    if (EPI == EPI_GV && col0 >= D_) { bp = bias2; coff = D_; gv_sig = false; }

    #pragma unroll
    for (int i = 0; i < 4; i++) {
        int rlo = row0 + wm * 64 + i * 16 + g;
        #pragma unroll
        for (int j = 0; j < 8; j++) {
            int col = col0 + wn * 64 + j * 8 + 2 * t;
            float2 bv = *(const float2*)(bp + col - coff);
            float lox = c[i][j][0] + bv.x, loy = c[i][j][1] + bv.y;
            float hix = c[i][j][2] + bv.x, hiy = c[i][j][3] + bv.y;
            size_t olo = (size_t)rlo * N + col;
            size_t ohi = olo + (size_t)8 * N;
            if (EPI == EPI_SIGMOID || (EPI == EPI_GV && gv_sig)) {
                lox = 1.f / (1.f + __expf(-lox)); loy = 1.f / (1.f + __expf(-loy));
                hix = 1.f / (1.f + __expf(-hix)); hiy = 1.f / (1.f + __expf(-hiy));
            } else if (EPI == EPI_GELU) {
                lox = 0.5f * lox * (1.f + erff(lox * 0.70710678118654752f));
                loy = 0.5f * loy * (1.f + erff(loy * 0.70710678118654752f));
                hix = 0.5f * hix * (1.f + erff(hix * 0.70710678118654752f));
                hiy = 0.5f * hiy * (1.f + erff(hiy * 0.70710678118654752f));
            } else if (EPI == EPI_ADD) {
                float2 a0 = __half22float2(*(const __half2*)(addsrc + olo));
                float2 a1 = __half22float2(*(const __half2*)(addsrc + ohi));
                lox += a0.x; loy += a0.y; hix += a1.x; hiy += a1.y;
            }
            store2(C + olo, lox, loy);
            store2(C + ohi, hix, hiy);
        }
    }
}

// =================== transpose (f32 -> f16): in[R,C] -> out[C,R] ===============
// 64-row x 32-col tiles; output rows stored as 32 x half2 = 128B per warp.
__global__ __launch_bounds__(256) void transpose_kernel(
    const float* __restrict__ in, __half* __restrict__ out, int R, int C)
{
    __shared__ float tbuf[64][33];
    int bx = blockIdx.x * 32;   // col block
    int by = blockIdx.y * 64;   // row block
    int tid  = threadIdx.x;
    int cl   = tid & 31;        // 0..31
    int rl   = tid >> 5;        // 0..7
    #pragma unroll
    for (int i = 0; i < 8; i++)
        tbuf[rl + i * 8][cl] = in[(size_t)(by + rl + i * 8) * C + bx + cl];
    __syncthreads();
    int warp = tid >> 5, lane = tid & 31;
    #pragma unroll
    for (int i = 0; i < 4; i++) {
        int crow = warp + i * 8;               // 0..31
        __half2 v = __floats2half2_rn(tbuf[2 * lane][crow], tbuf[2 * lane + 1][crow]);
        *(__half2*)(out + (size_t)(bx + crow) * R + by + 2 * lane) = v;
    }
}

// =================== LayerNorm (f32 in, f16 out) — used for LN1 ================
__global__ __launch_bounds__(256) void ln_kernel(
    const float* __restrict__ x, const float* __restrict__ gamma,
    const float* __restrict__ beta, __half* __restrict__ out)
{
    int row = blockIdx.x;
    int tid = threadIdx.x;
    const float4* xr = (const float4*)(x + (size_t)row * D_);
    float4 v = xr[tid];

    float s  = v.x + v.y + v.z + v.w;
    float sq = v.x*v.x + v.y*v.y + v.z*v.z + v.w*v.w;

    __shared__ float red0[8], red1[8];
    #pragma unroll
    for (int o = 16; o > 0; o >>= 1) {
        s  += __shfl_xor_sync(0xffffffffu, s,  o);
        sq += __shfl_xor_sync(0xffffffffu, sq, o);
    }
    if ((tid & 31) == 0) { red0[tid >> 5] = s; red1[tid >> 5] = sq; }
    __syncthreads();
    float a = 0.f, q = 0.f;
    #pragma unroll
    for (int w = 0; w < 8; w++) { a += red0[w]; q += red1[w]; }
    float mu = a * (1.0f / D_);
    float var = q * (1.0f / D_) - mu * mu;
    float rstd = rsqrtf(var + 1e-5f);

    float4 gv = ((const float4*)gamma)[tid];
    float4 bv = ((const float4*)beta)[tid];
    __half2* orow = (__half2*)(out + (size_t)row * D_);
    orow[tid * 2]     = __floats2half2_rn((v.x - mu) * rstd * gv.x + bv.x,
                                          (v.y - mu) * rstd * gv.y + bv.y);
    orow[tid * 2 + 1] = __floats2half2_rn((v.z - mu) * rstd * gv.z + bv.z,
                                          (v.w - mu) * rstd * gv.w + bv.w);
}

// =================== cumsum passes (g, v packed in gv[ROWS, 2D]) ===============
__global__ __launch_bounds__(256) void cums_partial(
    const __half* __restrict__ gv,
    float* __restrict__ pg, float* __restrict__ pgv)
{
    int bs  = blockIdx.x;            // b*NSEG + seg
    int b   = bs >> 7;
    int seg = bs & 127;
    int d   = (blockIdx.y * 256 + threadIdx.x) * 2;   // half2 lane
    size_t base = ((size_t)b * S_ + (size_t)seg * SEGLEN) * GVS + d;

    float2 sg = {0.f, 0.f}, sgv = {0.f, 0.f};
    #pragma unroll 4
    for (int s = 0; s < SEGLEN; s++) {
        float2 g2 = __half22float2(*(const __half2*)(gv + base + (size_t)s * GVS));
        float2 v2 = __half22float2(*(const __half2*)(gv + base + (size_t)s * GVS + D_));
        sg.x  += g2.x;        sg.y  += g2.y;
        sgv.x += g2.x * v2.x; sgv.y += g2.y * v2.y;
    }
    size_t o = (size_t)bs * D_ + d;
    *(float2*)(pg  + o) = sg;
    *(float2*)(pgv + o) = sgv;
}

// Exclusive scan over NSEG segments per (b,d), batched loads for MLP.
__global__ __launch_bounds__(256) void cums_scan(
    float* __restrict__ pg, float* __restrict__ pgv)
{
    int idx = blockIdx.x * 256 + threadIdx.x;  // 0 .. B_*D_-1
    int b = idx / D_;
    int d = idx % D_;
    size_t base = (size_t)b * NSEG * D_ + d;
    float rg = 0.f, rgv = 0.f;
    float tg[8], tv[8];
    for (int s0 = 0; s0 < NSEG; s0 += 8) {
        #pragma unroll
        for (int k = 0; k < 8; k++) {
            size_t o = base + (size_t)(s0 + k) * D_;
            tg[k] = pg[o];
            tv[k] = pgv[o];
        }
        #pragma unroll
        for (int k = 0; k < 8; k++) {
            size_t o = base + (size_t)(s0 + k) * D_;
            pg[o]  = rg;
            pgv[o] = rgv;
            rg  += tg[k];
            rgv += tv[k];
        }
    }
}

// ---- fused: inclusive cumsum-apply + residual (f16 xn) + LayerNorm2 (f16 h2) --
// 4 rows per __syncthreads (recurrence is per-thread; only LN mean needs sync).
__global__ __launch_bounds__(256) void cums_ln2(
    const __half* __restrict__ gv,
    const float* __restrict__ x,
    const float* __restrict__ pg, const float* __restrict__ pgv,
    const float* __restrict__ gamma, const float* __restrict__ beta,
    __half* __restrict__ xout, __half* __restrict__ h2)
{
    int bs  = blockIdx.x;            // b*NSEG + seg
    int b   = bs >> 7;
    int seg = bs & 127;
    int tid = threadIdx.x;
    int wid = tid >> 5, lid = tid & 31;

    size_t rowbase = (size_t)b * S_ + (size_t)seg * SEGLEN;
    size_t po = (size_t)bs * D_ + tid * 4;
    float4 rg  = *(const float4*)(pg  + po);
    float4 rgv = *(const float4*)(pgv + po);
    float4 gm  = ((const float4*)gamma)[tid];
    float4 bt  = ((const float4*)beta)[tid];

    __shared__ float red0[2][4][8], red1[2][4][8];

    for (int s0 = 0; s0 < SEGLEN; s0 += 4) {
        float4 xo[4];
        float ss[4], sq[4];
        #pragma unroll
        for (int k = 0; k < 4; k++) {
            size_t o  = (rowbase + s0 + k) * GVS + tid * 4;
            size_t od = (rowbase + s0 + k) * D_  + tid * 4;
            float2 ga = __half22float2(*(const __half2*)(gv + o));
            float2 gb = __half22float2(*(const __half2*)(gv + o + 2));
            float2 va = __half22float2(*(const __half2*)(gv + o + D_));
            float2 vb = __half22float2(*(const __half2*)(gv + o + D_ + 2));
            float4 x4 = *(const float4*)(x + od);

            rgv.x += ga.x * va.x;  rg.x += ga.x;
            rgv.y += ga.y * va.y;  rg.y += ga.y;
            rgv.z += gb.x * vb.x;  rg.z += gb.x;
            rgv.w += gb.y * vb.y;  rg.w += gb.y;

            xo[k].x = x4.x + rgv.x / (rg.x + 1e-6f);
            xo[k].y = x4.y + rgv.y / (rg.y + 1e-6f);
            xo[k].z = x4.z + rgv.z / (rg.z + 1e-6f);
            xo[k].w = x4.w + rgv.w / (rg.w + 1e-6f);
            __half2* xrow = (__half2*)(xout + od);
            xrow[0] = __floats2half2_rn(xo[k].x, xo[k].y);
            xrow[1] = __floats2half2_rn(xo[k].z, xo[k].w);

            ss[k] = xo[k].x + xo[k].y + xo[k].z + xo[k].w;
            sq[k] = xo[k].x*xo[k].x + xo[k].y*xo[k].y + xo[k].z*xo[k].z + xo[k].w*xo[k].w;
        }
        #pragma unroll
        for (int of = 16; of > 0; of >>= 1) {
            #pragma unroll
            for (int k = 0; k < 4; k++) {
                ss[k] += __shfl_xor_sync(0xffffffffu, ss[k], of);
                sq[k] += __shfl_xor_sync(0xffffffffu, sq[k], of);
            }
        }
        int pb = (s0 >> 2) & 1;
        if (lid == 0) {
            #pragma unroll
            for (int k = 0; k < 4; k++) { red0[pb][k][wid] = ss[k]; red1[pb][k][wid] = sq[k]; }
        }
        __syncthreads();
        #pragma unroll
        for (int k = 0; k < 4; k++) {
            float a = 0.f, q = 0.f;
            #pragma unroll
            for (int w = 0; w < 8; w++) { a += red0[pb][k][w]; q += red1[pb][k][w]; }
            float mu = a * (1.0f / D_);
            float var = q * (1.0f / D_) - mu * mu;
            float rstd = rsqrtf(var + 1e-5f);
            size_t od = (rowbase + s0 + k) * D_ + tid * 4;
            __half2* hrow = (__half2*)(h2 + od);
            hrow[0] = __floats2half2_rn((xo[k].x - mu) * rstd * gm.x + bt.x,
                                        (xo[k].y - mu) * rstd * gm.y + bt.y);
            hrow[1] = __floats2half2_rn((xo[k].z - mu) * rstd * gm.z + bt.z,
                                        (xo[k].w - mu) * rstd * gm.w + bt.w);
        }
    }
}

// =================== launch ====================================================
extern "C" void kernel_launch(void* const* d_in, const int* in_sizes, int n_in,
                              void* d_out, int out_size)
{
    const float* x       = (const float*)d_in[0];
    const float* ln1_g   = (const float*)d_in[1];
    const float* ln1_b   = (const float*)d_in[2];
    const float* ln2_g   = (const float*)d_in[3];
    const float* ln2_b   = (const float*)d_in[4];
    const float* gate_w  = (const float*)d_in[5];
    const float* gate_b  = (const float*)d_in[6];
    const float* value_w = (const float*)d_in[7];
    const float* value_b = (const float*)d_in[8];
    const float* ffn_w1  = (const float*)d_in[9];
    const float* ffn_b1  = (const float*)d_in[10];
    const float* ffn_w2  = (const float*)d_in[11];
    const float* ffn_b2  = (const float*)d_in[12];
    float* out = (float*)d_out;

    __half *h, *h2, *u, *gvwt, *w1t, *w2t, *gv, *xn;
    float *pg, *pgv;
    cudaGetSymbolAddress((void**)&h,    sc_h);
    cudaGetSymbolAddress((void**)&gv,   sc_gv);
    cudaGetSymbolAddress((void**)&xn,   sc_x);
    cudaGetSymbolAddress((void**)&h2,   sc_h2);
    cudaGetSymbolAddress((void**)&u,    sc_u);
    cudaGetSymbolAddress((void**)&pg,   sc_pg);
    cudaGetSymbolAddress((void**)&pgv,  sc_pgv);
    cudaGetSymbolAddress((void**)&gvwt, sc_gvwt);
    cudaGetSymbolAddress((void**)&w1t,  sc_w1t);
    cudaGetSymbolAddress((void**)&w2t,  sc_w2t);

    cudaFuncSetAttribute(gemm_mma<EPI_GV, __half>,   cudaFuncAttributeMaxDynamicSharedMemorySize, GEMM_SMEM);
    cudaFuncSetAttribute(gemm_mma<EPI_GELU, __half>, cudaFuncAttributeMaxDynamicSharedMemorySize, GEMM_SMEM);
    cudaFuncSetAttribute(gemm_mma<EPI_ADD, float>,   cudaFuncAttributeMaxDynamicSharedMemorySize, GEMM_SMEM);

    // 0. transpose weights to [N,K] fp16; gate+value concatenated to [2D, K]
    transpose_kernel<<<dim3(D_/32, D_/64),   256>>>(gate_w,  gvwt, D_, D_);
    transpose_kernel<<<dim3(D_/32, D_/64),   256>>>(value_w, gvwt + (size_t)D_ * D_, D_, D_);
    transpose_kernel<<<dim3(4*D_/32, D_/64), 256>>>(ffn_w1,  w1t, D_, 4*D_);
    transpose_kernel<<<dim3(D_/32, 4*D_/64), 256>>>(ffn_w2,  w2t, 4*D_, D_);

    // 1. h = LN1(x)  (fp16)
    ln_kernel<<<ROWS, 256>>>(x, ln1_g, ln1_b, h);

    // 2. fused gate|value GEMM -> gv[ROWS, 2D]
    dim3 gridGV(GVS / 128, ROWS / 128);
    gemm_mma<EPI_GV, __half><<<gridGV, 128, GEMM_SMEM>>>(
        h, gvwt, gate_b, value_b, nullptr, gv, ROWS, GVS, D_);

    // 4. memory residual + LN2 (fused)
    cums_partial<<<dim3(B_ * NSEG, D_ / 512), 256>>>(gv, pg, pgv);
    cums_scan<<<(B_ * D_) / 256, 256>>>(pg, pgv);
    cums_ln2<<<B_ * NSEG, 256>>>(gv, x, pg, pgv, ln2_g, ln2_b, xn, h2);

    // 6. u = gelu(h2 @ W1 + b1)  (fp16 out)
    dim3 gridFF1(4 * D_ / 128, ROWS / 128);
    gemm_mma<EPI_GELU, __half><<<gridFF1, 128, GEMM_SMEM>>>(
        h2, w1t, ffn_b1, nullptr, nullptr, u, ROWS, 4 * D_, D_);

    // 7. out = x_new + u @ W2 + b2
    dim3 gridFF2(D_ / 128, ROWS / 128);
    gemm_mma<EPI_ADD, float><<<gridFF2, 128, GEMM_SMEM>>>(
        u, w2t, ffn_b2, nullptr, xn, out, ROWS, D_, 4 * D_);
}

// round 14
// speedup vs baseline: 1.1890x; 1.0068x over previous
#include <cuda_runtime.h>
#include <cuda_fp16.h>
#include <math.h>
#include <stdint.h>

#define B_   4
#define S_   4096
#define D_   1024
#define ROWS (B_ * S_)        // 16384
#define NSEG 128
#define SEGLEN (S_ / NSEG)    // 32
#define GVS  (2 * D_)         // stride of combined gate|value buffer

// ---------------- scratch (static device globals; no allocations) -------------
__device__ __half sc_h [(size_t)ROWS * D_];      // LN1 output (fp16)
__device__ __half sc_gv[(size_t)ROWS * GVS];     // [g | v] combined (fp16)
__device__ __half sc_x [(size_t)ROWS * D_];      // x after memory residual (fp16)
__device__ __half sc_h2[(size_t)ROWS * D_];      // LN2 output (fp16)
__device__ __half sc_u [(size_t)ROWS * 4 * D_];  // gelu out (fp16)
__device__ float  sc_pg [(size_t)B_ * NSEG * D_];
__device__ float  sc_pgv[(size_t)B_ * NSEG * D_];
__device__ __half sc_gvwt[(size_t)2 * D_ * D_];  // [gate_w^T ; value_w^T]  [2D,K]
__device__ __half sc_w1t[(size_t)4 * D_ * D_];   // ffn_w1^T  fp16
__device__ __half sc_w2t[(size_t)D_ * 4 * D_];   // ffn_w2^T  fp16

// =================== helpers ====================================================
__device__ __forceinline__ uint32_t smem_u32(const void* p) {
    uint32_t a;
    asm("{ .reg .u64 t; cvta.to.shared.u64 t, %1; cvt.u32.u64 %0, t; }"
        : "=r"(a) : "l"(p));
    return a;
}

#define CP_COMMIT() asm volatile("cp.async.commit_group;" ::: "memory")
template <int N> __device__ __forceinline__ void cp_wait() {
    asm volatile("cp.async.wait_group %0;" :: "n"(N) : "memory");
}
__device__ __forceinline__ void cpasync16(uint32_t saddr, const void* g) {
    asm volatile("cp.async.cg.shared.global [%0], [%1], 16;"
                 :: "r"(saddr), "l"(g) : "memory");
}

// mma.sync m16n8k16 fp16 inputs, fp32 accumulate
__device__ __forceinline__ void mma_f16(float* c, const uint32_t* a, const uint32_t* b) {
    asm volatile(
        "mma.sync.aligned.m16n8k16.row.col.f32.f16.f16.f32 "
        "{%0,%1,%2,%3}, {%4,%5,%6,%7}, {%8,%9}, {%0,%1,%2,%3};"
        : "+f"(c[0]), "+f"(c[1]), "+f"(c[2]), "+f"(c[3])
        : "r"(a[0]), "r"(a[1]), "r"(a[2]), "r"(a[3]), "r"(b[0]), "r"(b[1]));
}

__device__ __forceinline__ void ldm4(uint32_t* r, uint32_t a) {
    asm volatile("ldmatrix.sync.aligned.m8n8.x4.shared.b16 {%0,%1,%2,%3}, [%4];"
                 : "=r"(r[0]), "=r"(r[1]), "=r"(r[2]), "=r"(r[3]) : "r"(a));
}

__device__ __forceinline__ void store2(float* p, float x, float y) {
    float2 t; t.x = x; t.y = y; *(float2*)p = t;
}
__device__ __forceinline__ void store2(__half* p, float x, float y) {
    *(__half2*)p = __floats2half2_rn(x, y);
}

// =================== mma.sync FP16 GEMM (round-9 proven config; UNCHANGED) =====
enum { EPI_NONE = 0, EPI_SIGMOID = 1, EPI_GELU = 2, EPI_ADD = 3, EPI_GV = 4 };

#define TILE_B   16384                 // 128 rows * 128 bytes (64 halfs)
#define STAGE_B  (2 * TILE_B)
#define NSTG     3
#define GEMM_SMEM (NSTG * STAGE_B)     // 98304 bytes

template <int EPI, typename OutT>
__global__ __launch_bounds__(128, 2) void gemm_mma(
    const __half* __restrict__ A, const __half* __restrict__ Bt,
    const float* __restrict__ bias, const float* __restrict__ bias2,
    const __half* __restrict__ addsrc,
    OutT* __restrict__ C, int M, int N, int K)
{
    extern __shared__ char smraw[];
    uint32_t smb = smem_u32(smraw);

    int tid  = threadIdx.x;
    int warp = tid >> 5, lane = tid & 31;
    int g = lane >> 2, t = lane & 3;
    int wm = warp >> 1, wn = warp & 1;          // 2 x 2 warp grid, 64x64 tiles
    int row0 = blockIdx.y * 128;
    int col0 = blockIdx.x * 128;
    int KCH  = K >> 6;                          // K chunks of 64 halfs (128B)

    int lr = tid >> 3;          // 0..15
    int lc = tid & 7;           // 0..7
    uint32_t st_off[8];
    #pragma unroll
    for (int i = 0; i < 8; i++) {
        int row = lr + 16 * i;
        st_off[i] = (uint32_t)(row * 128 + ((lc ^ (row & 7)) << 4));
    }
    const __half* gA = A  + (size_t)(row0 + lr) * K + lc * 8;
    const __half* gB = Bt + (size_t)(col0 + lr) * K + lc * 8;

    uint32_t rxor = (uint32_t)(lane & 7) << 4;
    uint32_t aoff[4], boff[4];
    #pragma unroll
    for (int i = 0; i < 4; i++) {
        int arow = wm * 64 + i * 16 + ((lane >> 3) & 1) * 8 + (lane & 7);
        aoff[i] = (uint32_t)arow * 128 + (((uint32_t)((lane >> 4) & 1) << 4) ^ rxor);
    }
    #pragma unroll
    for (int jp = 0; jp < 4; jp++) {
        int brow = wn * 64 + jp * 16 + (((lane >> 4) & 1) << 3) + (lane & 7);
        boff[jp] = (uint32_t)brow * 128 + (((uint32_t)((lane >> 3) & 1) << 4) ^ rxor);
    }

    float c[4][8][4];
    #pragma unroll
    for (int i = 0; i < 4; i++)
        #pragma unroll
        for (int j = 0; j < 8; j++)
            #pragma unroll
            for (int q = 0; q < 4; q++) c[i][j][q] = 0.f;

    #pragma unroll
    for (int s = 0; s < 2; s++) {
        uint32_t ab = smb + s * STAGE_B;
        uint32_t bb = ab + TILE_B;
        #pragma unroll
        for (int i = 0; i < 8; i++) {
            cpasync16(ab + st_off[i], gA + (size_t)i * 16 * K + s * 64);
            cpasync16(bb + st_off[i], gB + (size_t)i * 16 * K + s * 64);
        }
        CP_COMMIT();
    }

    for (int kc = 0; kc < KCH; kc++) {
        cp_wait<1>();
        __syncthreads();

        if (kc + 2 < KCH) {
            int s2 = (kc + 2) % NSTG;
            uint32_t ab = smb + s2 * STAGE_B;
            uint32_t bb = ab + TILE_B;
            #pragma unroll
            for (int i = 0; i < 8; i++) {
                cpasync16(ab + st_off[i], gA + (size_t)i * 16 * K + (kc + 2) * 64);
                cpasync16(bb + st_off[i], gB + (size_t)i * 16 * K + (kc + 2) * 64);
            }
        }
        CP_COMMIT();

        uint32_t sAst = smb + (kc % NSTG) * STAGE_B;
        uint32_t sBst = sAst + TILE_B;

        uint32_t af[2][4][4], bf[2][4][4];
        #pragma unroll
        for (int i = 0; i < 4; i++) ldm4(af[0][i], sAst + aoff[i]);
        #pragma unroll
        for (int jp = 0; jp < 4; jp++) ldm4(bf[0][jp], sBst + boff[jp]);

        #pragma unroll
        for (int ks = 0; ks < 4; ks++) {
            int cb = ks & 1, nb = cb ^ 1;
            if (ks < 3) {
                uint32_t kx = (uint32_t)(ks + 1) << 5;
                #pragma unroll
                for (int i = 0; i < 4; i++) ldm4(af[nb][i], sAst + (aoff[i] ^ kx));
                #pragma unroll
                for (int jp = 0; jp < 4; jp++) ldm4(bf[nb][jp], sBst + (boff[jp] ^ kx));
            }
            #pragma unroll
            for (int i = 0; i < 4; i++)
                #pragma unroll
                for (int jp = 0; jp < 4; jp++) {
                    mma_f16(c[i][2 * jp],     af[cb][i], &bf[cb][jp][0]);
                    mma_f16(c[i][2 * jp + 1], af[cb][i], &bf[cb][jp][2]);
                }
        }
    }

    const float* bp = bias;
    int coff = 0;
    bool gv_sig = true;
    if (EPI == EPI_GV && col0 >= D_) { bp = bias2; coff = D_; gv_sig = false; }

    #pragma unroll
    for (int i = 0; i < 4; i++) {
        int rlo = row0 + wm * 64 + i * 16 + g;
        #pragma unroll
        for (int j = 0; j < 8; j++) {
            int col = col0 + wn * 64 + j * 8 + 2 * t;
            float2 bv = *(const float2*)(bp + col - coff);
            float lox = c[i][j][0] + bv.x, loy = c[i][j][1] + bv.y;
            float hix = c[i][j][2] + bv.x, hiy = c[i][j][3] + bv.y;
            size_t olo = (size_t)rlo * N + col;
            size_t ohi = olo + (size_t)8 * N;
            if (EPI == EPI_SIGMOID || (EPI == EPI_GV && gv_sig)) {
                lox = 1.f / (1.f + __expf(-lox)); loy = 1.f / (1.f + __expf(-loy));
                hix = 1.f / (1.f + __expf(-hix)); hiy = 1.f / (1.f + __expf(-hiy));
            } else if (EPI == EPI_GELU) {
                lox = 0.5f * lox * (1.f + erff(lox * 0.70710678118654752f));
                loy = 0.5f * loy * (1.f + erff(loy * 0.70710678118654752f));
                hix = 0.5f * hix * (1.f + erff(hix * 0.70710678118654752f));
                hiy = 0.5f * hiy * (1.f + erff(hiy * 0.70710678118654752f));
            } else if (EPI == EPI_ADD) {
                float2 a0 = __half22float2(*(const __half2*)(addsrc + olo));
                float2 a1 = __half22float2(*(const __half2*)(addsrc + ohi));
                lox += a0.x; loy += a0.y; hix += a1.x; hiy += a1.y;
            }
            store2(C + olo, lox, loy);
            store2(C + ohi, hix, hiy);
        }
    }
}

// =================== fused prep: LN1 + all 4 weight transposes =================
// Task layout (flat blockIdx.x): [0, ROWS) = LN1 rows; then transpose tiles.
#define T_GATE_N   ((D_/32) * (D_/64))          // 512
#define T_VAL_N    ((D_/32) * (D_/64))          // 512
#define T_W1_N     ((4*D_/32) * (D_/64))        // 2048
#define T_W2_N     ((D_/32) * (4*D_/64))        // 2048
#define PREP_GRID  (ROWS + T_GATE_N + T_VAL_N + T_W1_N + T_W2_N)

__device__ __forceinline__ void transpose_body(
    const float* __restrict__ in, __half* __restrict__ out,
    int R, int C, int idx)
{
    __shared__ float tbuf[64][33];
    int nbx = C / 32;
    int bx = (idx % nbx) * 32;   // col block
    int by = (idx / nbx) * 64;   // row block
    int tid  = threadIdx.x;
    int cl   = tid & 31;
    int rl   = tid >> 5;
    #pragma unroll
    for (int i = 0; i < 8; i++)
        tbuf[rl + i * 8][cl] = in[(size_t)(by + rl + i * 8) * C + bx + cl];
    __syncthreads();
    int warp = tid >> 5, lane = tid & 31;
    #pragma unroll
    for (int i = 0; i < 4; i++) {
        int crow = warp + i * 8;
        __half2 v = __floats2half2_rn(tbuf[2 * lane][crow], tbuf[2 * lane + 1][crow]);
        *(__half2*)(out + (size_t)(bx + crow) * R + by + 2 * lane) = v;
    }
}

__device__ __forceinline__ void ln_body(
    const float* __restrict__ x, const float* __restrict__ gamma,
    const float* __restrict__ beta, __half* __restrict__ out, int row)
{
    int tid = threadIdx.x;
    const float4* xr = (const float4*)(x + (size_t)row * D_);
    float4 v = xr[tid];

    float s  = v.x + v.y + v.z + v.w;
    float sq = v.x*v.x + v.y*v.y + v.z*v.z + v.w*v.w;

    __shared__ float red0[8], red1[8];
    #pragma unroll
    for (int o = 16; o > 0; o >>= 1) {
        s  += __shfl_xor_sync(0xffffffffu, s,  o);
        sq += __shfl_xor_sync(0xffffffffu, sq, o);
    }
    if ((tid & 31) == 0) { red0[tid >> 5] = s; red1[tid >> 5] = sq; }
    __syncthreads();
    float a = 0.f, q = 0.f;
    #pragma unroll
    for (int w = 0; w < 8; w++) { a += red0[w]; q += red1[w]; }
    float mu = a * (1.0f / D_);
    float var = q * (1.0f / D_) - mu * mu;
    float rstd = rsqrtf(var + 1e-5f);

    float4 gv = ((const float4*)gamma)[tid];
    float4 bv = ((const float4*)beta)[tid];
    __half2* orow = (__half2*)(out + (size_t)row * D_);
    orow[tid * 2]     = __floats2half2_rn((v.x - mu) * rstd * gv.x + bv.x,
                                          (v.y - mu) * rstd * gv.y + bv.y);
    orow[tid * 2 + 1] = __floats2half2_rn((v.z - mu) * rstd * gv.z + bv.z,
                                          (v.w - mu) * rstd * gv.w + bv.w);
}

__global__ __launch_bounds__(256) void prep_kernel(
    const float* __restrict__ x,
    const float* __restrict__ ln1_g, const float* __restrict__ ln1_b,
    const float* __restrict__ gate_w, const float* __restrict__ value_w,
    const float* __restrict__ ffn_w1, const float* __restrict__ ffn_w2,
    __half* __restrict__ h, __half* __restrict__ gvwt,
    __half* __restrict__ w1t, __half* __restrict__ w2t)
{
    int blk = blockIdx.x;
    if (blk < ROWS) {
        ln_body(x, ln1_g, ln1_b, h, blk);
        return;
    }
    blk -= ROWS;
    if (blk < T_W1_N) { transpose_body(ffn_w1, w1t, D_, 4*D_, blk); return; }
    blk -= T_W1_N;
    if (blk < T_W2_N) { transpose_body(ffn_w2, w2t, 4*D_, D_, blk); return; }
    blk -= T_W2_N;
    if (blk < T_GATE_N) { transpose_body(gate_w, gvwt, D_, D_, blk); return; }
    blk -= T_GATE_N;
    transpose_body(value_w, gvwt + (size_t)D_ * D_, D_, D_, blk);
}

// =================== cumsum passes (g, v packed in gv[ROWS, 2D]) ===============
__global__ __launch_bounds__(256) void cums_partial(
    const __half* __restrict__ gv,
    float* __restrict__ pg, float* __restrict__ pgv)
{
    int bs  = blockIdx.x;
    int b   = bs >> 7;
    int seg = bs & 127;
    int d   = (blockIdx.y * 256 + threadIdx.x) * 2;
    size_t base = ((size_t)b * S_ + (size_t)seg * SEGLEN) * GVS + d;

    float2 sg = {0.f, 0.f}, sgv = {0.f, 0.f};
    #pragma unroll 4
    for (int s = 0; s < SEGLEN; s++) {
        float2 g2 = __half22float2(*(const __half2*)(gv + base + (size_t)s * GVS));
        float2 v2 = __half22float2(*(const __half2*)(gv + base + (size_t)s * GVS + D_));
        sg.x  += g2.x;        sg.y  += g2.y;
        sgv.x += g2.x * v2.x; sgv.y += g2.y * v2.y;
    }
    size_t o = (size_t)bs * D_ + d;
    *(float2*)(pg  + o) = sg;
    *(float2*)(pgv + o) = sgv;
}

__global__ __launch_bounds__(256) void cums_scan(
    float* __restrict__ pg, float* __restrict__ pgv)
{
    int idx = blockIdx.x * 256 + threadIdx.x;
    int b = idx / D_;
    int d = idx % D_;
    size_t base = (size_t)b * NSEG * D_ + d;
    float rg = 0.f, rgv = 0.f;
    float tg[8], tv[8];
    for (int s0 = 0; s0 < NSEG; s0 += 8) {
        #pragma unroll
        for (int k = 0; k < 8; k++) {
            size_t o = base + (size_t)(s0 + k) * D_;
            tg[k] = pg[o];
            tv[k] = pgv[o];
        }
        #pragma unroll
        for (int k = 0; k < 8; k++) {
            size_t o = base + (size_t)(s0 + k) * D_;
            pg[o]  = rg;
            pgv[o] = rgv;
            rg  += tg[k];
            rgv += tv[k];
        }
    }
}

__global__ __launch_bounds__(256) void cums_ln2(
    const __half* __restrict__ gv,
    const float* __restrict__ x,
    const float* __restrict__ pg, const float* __restrict__ pgv,
    const float* __restrict__ gamma, const float* __restrict__ beta,
    __half* __restrict__ xout, __half* __restrict__ h2)
{
    int bs  = blockIdx.x;
    int b   = bs >> 7;
    int seg = bs & 127;
    int tid = threadIdx.x;
    int wid = tid >> 5, lid = tid & 31;

    size_t rowbase = (size_t)b * S_ + (size_t)seg * SEGLEN;
    size_t po = (size_t)bs * D_ + tid * 4;
    float4 rg  = *(const float4*)(pg  + po);
    float4 rgv = *(const float4*)(pgv + po);
    float4 gm  = ((const float4*)gamma)[tid];
    float4 bt  = ((const float4*)beta)[tid];

    __shared__ float red0[2][4][8], red1[2][4][8];

    for (int s0 = 0; s0 < SEGLEN; s0 += 4) {
        float4 xo[4];
        float ss[4], sq[4];
        #pragma unroll
        for (int k = 0; k < 4; k++) {
            size_t o  = (rowbase + s0 + k) * GVS + tid * 4;
            size_t od = (rowbase + s0 + k) * D_  + tid * 4;
            float2 ga = __half22float2(*(const __half2*)(gv + o));
            float2 gb = __half22float2(*(const __half2*)(gv + o + 2));
            float2 va = __half22float2(*(const __half2*)(gv + o + D_));
            float2 vb = __half22float2(*(const __half2*)(gv + o + D_ + 2));
            float4 x4 = *(const float4*)(x + od);

            rgv.x += ga.x * va.x;  rg.x += ga.x;
            rgv.y += ga.y * va.y;  rg.y += ga.y;
            rgv.z += gb.x * vb.x;  rg.z += gb.x;
            rgv.w += gb.y * vb.y;  rg.w += gb.y;

            xo[k].x = x4.x + rgv.x / (rg.x + 1e-6f);
            xo[k].y = x4.y + rgv.y / (rg.y + 1e-6f);
            xo[k].z = x4.z + rgv.z / (rg.z + 1e-6f);
            xo[k].w = x4.w + rgv.w / (rg.w + 1e-6f);
            __half2* xrow = (__half2*)(xout + od);
            xrow[0] = __floats2half2_rn(xo[k].x, xo[k].y);
            xrow[1] = __floats2half2_rn(xo[k].z, xo[k].w);

            ss[k] = xo[k].x + xo[k].y + xo[k].z + xo[k].w;
            sq[k] = xo[k].x*xo[k].x + xo[k].y*xo[k].y + xo[k].z*xo[k].z + xo[k].w*xo[k].w;
        }
        #pragma unroll
        for (int of = 16; of > 0; of >>= 1) {
            #pragma unroll
            for (int k = 0; k < 4; k++) {
                ss[k] += __shfl_xor_sync(0xffffffffu, ss[k], of);
                sq[k] += __shfl_xor_sync(0xffffffffu, sq[k], of);
            }
        }
        int pb = (s0 >> 2) & 1;
        if (lid == 0) {
            #pragma unroll
            for (int k = 0; k < 4; k++) { red0[pb][k][wid] = ss[k]; red1[pb][k][wid] = sq[k]; }
        }
        __syncthreads();
        #pragma unroll
        for (int k = 0; k < 4; k++) {
            float a = 0.f, q = 0.f;
            #pragma unroll
            for (int w = 0; w < 8; w++) { a += red0[pb][k][w]; q += red1[pb][k][w]; }
            float mu = a * (1.0f / D_);
            float var = q * (1.0f / D_) - mu * mu;
            float rstd = rsqrtf(var + 1e-5f);
            size_t od = (rowbase + s0 + k) * D_ + tid * 4;
            __half2* hrow = (__half2*)(h2 + od);
            hrow[0] = __floats2half2_rn((xo[k].x - mu) * rstd * gm.x + bt.x,
                                        (xo[k].y - mu) * rstd * gm.y + bt.y);
            hrow[1] = __floats2half2_rn((xo[k].z - mu) * rstd * gm.z + bt.z,
                                        (xo[k].w - mu) * rstd * gm.w + bt.w);
        }
    }
}

// =================== launch ====================================================
extern "C" void kernel_launch(void* const* d_in, const int* in_sizes, int n_in,
                              void* d_out, int out_size)
{
    const float* x       = (const float*)d_in[0];
    const float* ln1_g   = (const float*)d_in[1];
    const float* ln1_b   = (const float*)d_in[2];
    const float* ln2_g   = (const float*)d_in[3];
    const float* ln2_b   = (const float*)d_in[4];
    const float* gate_w  = (const float*)d_in[5];
    const float* gate_b  = (const float*)d_in[6];
    const float* value_w = (const float*)d_in[7];
    const float* value_b = (const float*)d_in[8];
    const float* ffn_w1  = (const float*)d_in[9];
    const float* ffn_b1  = (const float*)d_in[10];
    const float* ffn_w2  = (const float*)d_in[11];
    const float* ffn_b2  = (const float*)d_in[12];
    float* out = (float*)d_out;

    __half *h, *h2, *u, *gvwt, *w1t, *w2t, *gv, *xn;
    float *pg, *pgv;
    cudaGetSymbolAddress((void**)&h,    sc_h);
    cudaGetSymbolAddress((void**)&gv,   sc_gv);
    cudaGetSymbolAddress((void**)&xn,   sc_x);
    cudaGetSymbolAddress((void**)&h2,   sc_h2);
    cudaGetSymbolAddress((void**)&u,    sc_u);
    cudaGetSymbolAddress((void**)&pg,   sc_pg);
    cudaGetSymbolAddress((void**)&pgv,  sc_pgv);
    cudaGetSymbolAddress((void**)&gvwt, sc_gvwt);
    cudaGetSymbolAddress((void**)&w1t,  sc_w1t);
    cudaGetSymbolAddress((void**)&w2t,  sc_w2t);

    cudaFuncSetAttribute(gemm_mma<EPI_GV, __half>,   cudaFuncAttributeMaxDynamicSharedMemorySize, GEMM_SMEM);
    cudaFuncSetAttribute(gemm_mma<EPI_GELU, __half>, cudaFuncAttributeMaxDynamicSharedMemorySize, GEMM_SMEM);
    cudaFuncSetAttribute(gemm_mma<EPI_ADD, float>,   cudaFuncAttributeMaxDynamicSharedMemorySize, GEMM_SMEM);

    // 0+1. fused prep: LN1 + all weight transposes (one launch)
    prep_kernel<<<PREP_GRID, 256>>>(x, ln1_g, ln1_b, gate_w, value_w,
                                    ffn_w1, ffn_w2, h, gvwt, w1t, w2t);

    // 2. fused gate|value GEMM -> gv[ROWS, 2D]
    dim3 gridGV(GVS / 128, ROWS / 128);
    gemm_mma<EPI_GV, __half><<<gridGV, 128, GEMM_SMEM>>>(
        h, gvwt, gate_b, value_b, nullptr, gv, ROWS, GVS, D_);

    // 4. memory residual + LN2 (fused)
    cums_partial<<<dim3(B_ * NSEG, D_ / 512), 256>>>(gv, pg, pgv);
    cums_scan<<<(B_ * D_) / 256, 256>>>(pg, pgv);
    cums_ln2<<<B_ * NSEG, 256>>>(gv, x, pg, pgv, ln2_g, ln2_b, xn, h2);

    // 6. u = gelu(h2 @ W1 + b1)  (fp16 out)
    dim3 gridFF1(4 * D_ / 128, ROWS / 128);
    gemm_mma<EPI_GELU, __half><<<gridFF1, 128, GEMM_SMEM>>>(
        h2, w1t, ffn_b1, nullptr, nullptr, u, ROWS, 4 * D_, D_);

    // 7. out = x_new + u @ W2 + b2
    dim3 gridFF2(D_ / 128, ROWS / 128);
    gemm_mma<EPI_ADD, float><<<gridFF2, 128, GEMM_SMEM>>>(
        u, w2t, ffn_b2, nullptr, xn, out, ROWS, D_, 4 * D_);
}

// round 15
// speedup vs baseline: 1.1916x; 1.0022x over previous
#include <cuda_runtime.h>
#include <cuda_fp16.h>
#include <math.h>
#include <stdint.h>

#define B_   4
#define S_   4096
#define D_   1024
#define ROWS (B_ * S_)        // 16384
#define NSEG 128
#define SEGLEN (S_ / NSEG)    // 32
#define GVS  (2 * D_)         // stride of combined gate|value buffer

// ---------------- scratch (static device globals; no allocations) -------------
__device__ __half sc_h [(size_t)ROWS * D_];      // LN1 output (fp16)
__device__ __half sc_gv[(size_t)ROWS * GVS];     // [g | v] combined (fp16)
__device__ __half sc_x [(size_t)ROWS * D_];      // x after memory residual (fp16)
__device__ __half sc_h2[(size_t)ROWS * D_];      // LN2 output (fp16)
__device__ __half sc_u [(size_t)ROWS * 4 * D_];  // gelu out (fp16)
__device__ float  sc_pg [(size_t)B_ * NSEG * D_];
__device__ float  sc_pgv[(size_t)B_ * NSEG * D_];
__device__ __half sc_gvwt[(size_t)2 * D_ * D_];  // [gate_w^T ; value_w^T]  [2D,K]
__device__ __half sc_w1t[(size_t)4 * D_ * D_];   // ffn_w1^T  fp16
__device__ __half sc_w2t[(size_t)D_ * 4 * D_];   // ffn_w2^T  fp16

// =================== helpers ====================================================
__device__ __forceinline__ uint32_t smem_u32(const void* p) {
    uint32_t a;
    asm("{ .reg .u64 t; cvta.to.shared.u64 t, %1; cvt.u32.u64 %0, t; }"
        : "=r"(a) : "l"(p));
    return a;
}

#define CP_COMMIT() asm volatile("cp.async.commit_group;" ::: "memory")
template <int N> __device__ __forceinline__ void cp_wait() {
    asm volatile("cp.async.wait_group %0;" :: "n"(N) : "memory");
}
__device__ __forceinline__ void cpasync16(uint32_t saddr, const void* g) {
    asm volatile("cp.async.cg.shared.global [%0], [%1], 16;"
                 :: "r"(saddr), "l"(g) : "memory");
}

// mma.sync m16n8k16 fp16 inputs, fp32 accumulate
__device__ __forceinline__ void mma_f16(float* c, const uint32_t* a, const uint32_t* b) {
    asm volatile(
        "mma.sync.aligned.m16n8k16.row.col.f32.f16.f16.f32 "
        "{%0,%1,%2,%3}, {%4,%5,%6,%7}, {%8,%9}, {%0,%1,%2,%3};"
        : "+f"(c[0]), "+f"(c[1]), "+f"(c[2]), "+f"(c[3])
        : "r"(a[0]), "r"(a[1]), "r"(a[2]), "r"(a[3]), "r"(b[0]), "r"(b[1]));
}

__device__ __forceinline__ void ldm4(uint32_t* r, uint32_t a) {
    asm volatile("ldmatrix.sync.aligned.m8n8.x4.shared.b16 {%0,%1,%2,%3}, [%4];"
                 : "=r"(r[0]), "=r"(r[1]), "=r"(r[2]), "=r"(r[3]) : "r"(a));
}

__device__ __forceinline__ void store2(float* p, float x, float y) {
    float2 t; t.x = x; t.y = y; *(float2*)p = t;
}
__device__ __forceinline__ void store2(__half* p, float x, float y) {
    *(__half2*)p = __floats2half2_rn(x, y);
}

// =================== mma.sync FP16 GEMM (round-9 proven config; UNCHANGED) =====
enum { EPI_NONE = 0, EPI_SIGMOID = 1, EPI_GELU = 2, EPI_ADD = 3, EPI_GV = 4 };

#define TILE_B   16384                 // 128 rows * 128 bytes (64 halfs)
#define STAGE_B  (2 * TILE_B)
#define NSTG     3
#define GEMM_SMEM (NSTG * STAGE_B)     // 98304 bytes

template <int EPI, typename OutT>
__global__ __launch_bounds__(128, 2) void gemm_mma(
    const __half* __restrict__ A, const __half* __restrict__ Bt,
    const float* __restrict__ bias, const float* __restrict__ bias2,
    const __half* __restrict__ addsrc,
    OutT* __restrict__ C, int M, int N, int K)
{
    extern __shared__ char smraw[];
    uint32_t smb = smem_u32(smraw);

    int tid  = threadIdx.x;
    int warp = tid >> 5, lane = tid & 31;
    int g = lane >> 2, t = lane & 3;
    int wm = warp >> 1, wn = warp & 1;          // 2 x 2 warp grid, 64x64 tiles
    int row0 = blockIdx.y * 128;
    int col0 = blockIdx.x * 128;
    int KCH  = K >> 6;                          // K chunks of 64 halfs (128B)

    int lr = tid >> 3;          // 0..15
    int lc = tid & 7;           // 0..7
    uint32_t st_off[8];
    #pragma unroll
    for (int i = 0; i < 8; i++) {
        int row = lr + 16 * i;
        st_off[i] = (uint32_t)(row * 128 + ((lc ^ (row & 7)) << 4));
    }
    const __half* gA = A  + (size_t)(row0 + lr) * K + lc * 8;
    const __half* gB = Bt + (size_t)(col0 + lr) * K + lc * 8;

    uint32_t rxor = (uint32_t)(lane & 7) << 4;
    uint32_t aoff[4], boff[4];
    #pragma unroll
    for (int i = 0; i < 4; i++) {
        int arow = wm * 64 + i * 16 + ((lane >> 3) & 1) * 8 + (lane & 7);
        aoff[i] = (uint32_t)arow * 128 + (((uint32_t)((lane >> 4) & 1) << 4) ^ rxor);
    }
    #pragma unroll
    for (int jp = 0; jp < 4; jp++) {
        int brow = wn * 64 + jp * 16 + (((lane >> 4) & 1) << 3) + (lane & 7);
        boff[jp] = (uint32_t)brow * 128 + (((uint32_t)((lane >> 3) & 1) << 4) ^ rxor);
    }

    float c[4][8][4];
    #pragma unroll
    for (int i = 0; i < 4; i++)
        #pragma unroll
        for (int j = 0; j < 8; j++)
            #pragma unroll
            for (int q = 0; q < 4; q++) c[i][j][q] = 0.f;

    #pragma unroll
    for (int s = 0; s < 2; s++) {
        uint32_t ab = smb + s * STAGE_B;
        uint32_t bb = ab + TILE_B;
        #pragma unroll
        for (int i = 0; i < 8; i++) {
            cpasync16(ab + st_off[i], gA + (size_t)i * 16 * K + s * 64);
            cpasync16(bb + st_off[i], gB + (size_t)i * 16 * K + s * 64);
        }
        CP_COMMIT();
    }

    for (int kc = 0; kc < KCH; kc++) {
        cp_wait<1>();
        __syncthreads();

        if (kc + 2 < KCH) {
            int s2 = (kc + 2) % NSTG;
            uint32_t ab = smb + s2 * STAGE_B;
            uint32_t bb = ab + TILE_B;
            #pragma unroll
            for (int i = 0; i < 8; i++) {
                cpasync16(ab + st_off[i], gA + (size_t)i * 16 * K + (kc + 2) * 64);
                cpasync16(bb + st_off[i], gB + (size_t)i * 16 * K + (kc + 2) * 64);
            }
        }
        CP_COMMIT();

        uint32_t sAst = smb + (kc % NSTG) * STAGE_B;
        uint32_t sBst = sAst + TILE_B;

        uint32_t af[2][4][4], bf[2][4][4];
        #pragma unroll
        for (int i = 0; i < 4; i++) ldm4(af[0][i], sAst + aoff[i]);
        #pragma unroll
        for (int jp = 0; jp < 4; jp++) ldm4(bf[0][jp], sBst + boff[jp]);

        #pragma unroll
        for (int ks = 0; ks < 4; ks++) {
            int cb = ks & 1, nb = cb ^ 1;
            if (ks < 3) {
                uint32_t kx = (uint32_t)(ks + 1) << 5;
                #pragma unroll
                for (int i = 0; i < 4; i++) ldm4(af[nb][i], sAst + (aoff[i] ^ kx));
                #pragma unroll
                for (int jp = 0; jp < 4; jp++) ldm4(bf[nb][jp], sBst + (boff[jp] ^ kx));
            }
            #pragma unroll
            for (int i = 0; i < 4; i++)
                #pragma unroll
                for (int jp = 0; jp < 4; jp++) {
                    mma_f16(c[i][2 * jp],     af[cb][i], &bf[cb][jp][0]);
                    mma_f16(c[i][2 * jp + 1], af[cb][i], &bf[cb][jp][2]);
                }
        }
    }

    const float* bp = bias;
    int coff = 0;
    bool gv_sig = true;
    if (EPI == EPI_GV && col0 >= D_) { bp = bias2; coff = D_; gv_sig = false; }

    #pragma unroll
    for (int i = 0; i < 4; i++) {
        int rlo = row0 + wm * 64 + i * 16 + g;
        #pragma unroll
        for (int j = 0; j < 8; j++) {
            int col = col0 + wn * 64 + j * 8 + 2 * t;
            float2 bv = *(const float2*)(bp + col - coff);
            float lox = c[i][j][0] + bv.x, loy = c[i][j][1] + bv.y;
            float hix = c[i][j][2] + bv.x, hiy = c[i][j][3] + bv.y;
            size_t olo = (size_t)rlo * N + col;
            size_t ohi = olo + (size_t)8 * N;
            if (EPI == EPI_SIGMOID || (EPI == EPI_GV && gv_sig)) {
                lox = 1.f / (1.f + __expf(-lox)); loy = 1.f / (1.f + __expf(-loy));
                hix = 1.f / (1.f + __expf(-hix)); hiy = 1.f / (1.f + __expf(-hiy));
            } else if (EPI == EPI_GELU) {
                lox = 0.5f * lox * (1.f + erff(lox * 0.70710678118654752f));
                loy = 0.5f * loy * (1.f + erff(loy * 0.70710678118654752f));
                hix = 0.5f * hix * (1.f + erff(hix * 0.70710678118654752f));
                hiy = 0.5f * hiy * (1.f + erff(hiy * 0.70710678118654752f));
            } else if (EPI == EPI_ADD) {
                float2 a0 = __half22float2(*(const __half2*)(addsrc + olo));
                float2 a1 = __half22float2(*(const __half2*)(addsrc + ohi));
                lox += a0.x; loy += a0.y; hix += a1.x; hiy += a1.y;
            }
            store2(C + olo, lox, loy);
            store2(C + ohi, hix, hiy);
        }
    }
}

// =================== fused prep: LN1 + all 4 weight transposes =================
#define T_GATE_N   ((D_/32) * (D_/64))          // 512
#define T_VAL_N    ((D_/32) * (D_/64))          // 512
#define T_W1_N     ((4*D_/32) * (D_/64))        // 2048
#define T_W2_N     ((D_/32) * (4*D_/64))        // 2048
#define PREP_GRID  (ROWS + T_GATE_N + T_VAL_N + T_W1_N + T_W2_N)

__device__ __forceinline__ void transpose_body(
    const float* __restrict__ in, __half* __restrict__ out,
    int R, int C, int idx)
{
    __shared__ float tbuf[64][33];
    int nbx = C / 32;
    int bx = (idx % nbx) * 32;   // col block
    int by = (idx / nbx) * 64;   // row block
    int tid  = threadIdx.x;
    int cl   = tid & 31;
    int rl   = tid >> 5;
    #pragma unroll
    for (int i = 0; i < 8; i++)
        tbuf[rl + i * 8][cl] = in[(size_t)(by + rl + i * 8) * C + bx + cl];
    __syncthreads();
    int warp = tid >> 5, lane = tid & 31;
    #pragma unroll
    for (int i = 0; i < 4; i++) {
        int crow = warp + i * 8;
        __half2 v = __floats2half2_rn(tbuf[2 * lane][crow], tbuf[2 * lane + 1][crow]);
        *(__half2*)(out + (size_t)(bx + crow) * R + by + 2 * lane) = v;
    }
}

__device__ __forceinline__ void ln_body(
    const float* __restrict__ x, const float* __restrict__ gamma,
    const float* __restrict__ beta, __half* __restrict__ out, int row)
{
    int tid = threadIdx.x;
    const float4* xr = (const float4*)(x + (size_t)row * D_);
    float4 v = xr[tid];

    float s  = v.x + v.y + v.z + v.w;
    float sq = v.x*v.x + v.y*v.y + v.z*v.z + v.w*v.w;

    __shared__ float red0[8], red1[8];
    #pragma unroll
    for (int o = 16; o > 0; o >>= 1) {
        s  += __shfl_xor_sync(0xffffffffu, s,  o);
        sq += __shfl_xor_sync(0xffffffffu, sq, o);
    }
    if ((tid & 31) == 0) { red0[tid >> 5] = s; red1[tid >> 5] = sq; }
    __syncthreads();
    float a = 0.f, q = 0.f;
    #pragma unroll
    for (int w = 0; w < 8; w++) { a += red0[w]; q += red1[w]; }
    float mu = a * (1.0f / D_);
    float var = q * (1.0f / D_) - mu * mu;
    float rstd = rsqrtf(var + 1e-5f);

    float4 gv = ((const float4*)gamma)[tid];
    float4 bv = ((const float4*)beta)[tid];
    __half2* orow = (__half2*)(out + (size_t)row * D_);
    orow[tid * 2]     = __floats2half2_rn((v.x - mu) * rstd * gv.x + bv.x,
                                          (v.y - mu) * rstd * gv.y + bv.y);
    orow[tid * 2 + 1] = __floats2half2_rn((v.z - mu) * rstd * gv.z + bv.z,
                                          (v.w - mu) * rstd * gv.w + bv.w);
}

__global__ __launch_bounds__(256) void prep_kernel(
    const float* __restrict__ x,
    const float* __restrict__ ln1_g, const float* __restrict__ ln1_b,
    const float* __restrict__ gate_w, const float* __restrict__ value_w,
    const float* __restrict__ ffn_w1, const float* __restrict__ ffn_w2,
    __half* __restrict__ h, __half* __restrict__ gvwt,
    __half* __restrict__ w1t, __half* __restrict__ w2t)
{
    int blk = blockIdx.x;
    if (blk < ROWS) {
        ln_body(x, ln1_g, ln1_b, h, blk);
        return;
    }
    blk -= ROWS;
    if (blk < T_W1_N) { transpose_body(ffn_w1, w1t, D_, 4*D_, blk); return; }
    blk -= T_W1_N;
    if (blk < T_W2_N) { transpose_body(ffn_w2, w2t, 4*D_, D_, blk); return; }
    blk -= T_W2_N;
    if (blk < T_GATE_N) { transpose_body(gate_w, gvwt, D_, D_, blk); return; }
    blk -= T_GATE_N;
    transpose_body(value_w, gvwt + (size_t)D_ * D_, D_, D_, blk);
}

// =================== cumsum passes (g, v packed in gv[ROWS, 2D]) ===============
__global__ __launch_bounds__(256) void cums_partial(
    const __half* __restrict__ gv,
    float* __restrict__ pg, float* __restrict__ pgv)
{
    int bs  = blockIdx.x;
    int b   = bs >> 7;
    int seg = bs & 127;
    int d   = (blockIdx.y * 256 + threadIdx.x) * 2;
    size_t base = ((size_t)b * S_ + (size_t)seg * SEGLEN) * GVS + d;

    float2 sg = {0.f, 0.f}, sgv = {0.f, 0.f};
    #pragma unroll 4
    for (int s = 0; s < SEGLEN; s++) {
        float2 g2 = __half22float2(*(const __half2*)(gv + base + (size_t)s * GVS));
        float2 v2 = __half22float2(*(const __half2*)(gv + base + (size_t)s * GVS + D_));
        sg.x  += g2.x;        sg.y  += g2.y;
        sgv.x += g2.x * v2.x; sgv.y += g2.y * v2.y;
    }
    size_t o = (size_t)bs * D_ + d;
    *(float2*)(pg  + o) = sg;
    *(float2*)(pgv + o) = sgv;
}

// Exclusive scan over NSEG segments: ONE WARP per (b,d); lane l owns segs
// [4l, 4l+4). Local sums -> exclusive warp scan via shfl_up -> write back.
__global__ __launch_bounds__(256) void cums_scan(
    float* __restrict__ pg, float* __restrict__ pgv)
{
    int wgid = (blockIdx.x * 256 + threadIdx.x) >> 5;   // 0 .. B_*D_-1
    int lane = threadIdx.x & 31;
    int b = wgid >> 10;            // / D_
    int d = wgid & (D_ - 1);       // % D_
    size_t base = ((size_t)b * NSEG + lane * 4) * D_ + d;

    float tg[4], tv[4];
    #pragma unroll
    for (int k = 0; k < 4; k++) {
        tg[k] = pg [base + (size_t)k * D_];
        tv[k] = pgv[base + (size_t)k * D_];
    }
    float sg = tg[0] + tg[1] + tg[2] + tg[3];
    float sv = tv[0] + tv[1] + tv[2] + tv[3];

    // inclusive warp scan of chunk totals
    float ig = sg, iv = sv;
    #pragma unroll
    for (int off = 1; off < 32; off <<= 1) {
        float ng = __shfl_up_sync(0xffffffffu, ig, off);
        float nv = __shfl_up_sync(0xffffffffu, iv, off);
        if (lane >= off) { ig += ng; iv += nv; }
    }
    float rg = ig - sg;            // exclusive prefix of this lane's chunk
    float rv = iv - sv;

    #pragma unroll
    for (int k = 0; k < 4; k++) {
        pg [base + (size_t)k * D_] = rg;
        pgv[base + (size_t)k * D_] = rv;
        rg += tg[k];
        rv += tv[k];
    }
}

__global__ __launch_bounds__(256) void cums_ln2(
    const __half* __restrict__ gv,
    const float* __restrict__ x,
    const float* __restrict__ pg, const float* __restrict__ pgv,
    const float* __restrict__ gamma, const float* __restrict__ beta,
    __half* __restrict__ xout, __half* __restrict__ h2)
{
    int bs  = blockIdx.x;
    int b   = bs >> 7;
    int seg = bs & 127;
    int tid = threadIdx.x;
    int wid = tid >> 5, lid = tid & 31;

    size_t rowbase = (size_t)b * S_ + (size_t)seg * SEGLEN;
    size_t po = (size_t)bs * D_ + tid * 4;
    float4 rg  = *(const float4*)(pg  + po);
    float4 rgv = *(const float4*)(pgv + po);
    float4 gm  = ((const float4*)gamma)[tid];
    float4 bt  = ((const float4*)beta)[tid];

    __shared__ float red0[2][4][8], red1[2][4][8];

    for (int s0 = 0; s0 < SEGLEN; s0 += 4) {
        float4 xo[4];
        float ss[4], sq[4];
        #pragma unroll
        for (int k = 0; k < 4; k++) {
            size_t o  = (rowbase + s0 + k) * GVS + tid * 4;
            size_t od = (rowbase + s0 + k) * D_  + tid * 4;
            float2 ga = __half22float2(*(const __half2*)(gv + o));
            float2 gb = __half22float2(*(const __half2*)(gv + o + 2));
            float2 va = __half22float2(*(const __half2*)(gv + o + D_));
            float2 vb = __half22float2(*(const __half2*)(gv + o + D_ + 2));
            float4 x4 = *(const float4*)(x + od);

            rgv.x += ga.x * va.x;  rg.x += ga.x;
            rgv.y += ga.y * va.y;  rg.y += ga.y;
            rgv.z += gb.x * vb.x;  rg.z += gb.x;
            rgv.w += gb.y * vb.y;  rg.w += gb.y;

            xo[k].x = x4.x + rgv.x / (rg.x + 1e-6f);
            xo[k].y = x4.y + rgv.y / (rg.y + 1e-6f);
            xo[k].z = x4.z + rgv.z / (rg.z + 1e-6f);
            xo[k].w = x4.w + rgv.w / (rg.w + 1e-6f);
            __half2* xrow = (__half2*)(xout + od);
            xrow[0] = __floats2half2_rn(xo[k].x, xo[k].y);
            xrow[1] = __floats2half2_rn(xo[k].z, xo[k].w);

            ss[k] = xo[k].x + xo[k].y + xo[k].z + xo[k].w;
            sq[k] = xo[k].x*xo[k].x + xo[k].y*xo[k].y + xo[k].z*xo[k].z + xo[k].w*xo[k].w;
        }
        #pragma unroll
        for (int of = 16; of > 0; of >>= 1) {
            #pragma unroll
            for (int k = 0; k < 4; k++) {
                ss[k] += __shfl_xor_sync(0xffffffffu, ss[k], of);
                sq[k] += __shfl_xor_sync(0xffffffffu, sq[k], of);
            }
        }
        int pb = (s0 >> 2) & 1;
        if (lid == 0) {
            #pragma unroll
            for (int k = 0; k < 4; k++) { red0[pb][k][wid] = ss[k]; red1[pb][k][wid] = sq[k]; }
        }
        __syncthreads();
        #pragma unroll
        for (int k = 0; k < 4; k++) {
            float a = 0.f, q = 0.f;
            #pragma unroll
            for (int w = 0; w < 8; w++) { a += red0[pb][k][w]; q += red1[pb][k][w]; }
            float mu = a * (1.0f / D_);
            float var = q * (1.0f / D_) - mu * mu;
            float rstd = rsqrtf(var + 1e-5f);
            size_t od = (rowbase + s0 + k) * D_ + tid * 4;
            __half2* hrow = (__half2*)(h2 + od);
            hrow[0] = __floats2half2_rn((xo[k].x - mu) * rstd * gm.x + bt.x,
                                        (xo[k].y - mu) * rstd * gm.y + bt.y);
            hrow[1] = __floats2half2_rn((xo[k].z - mu) * rstd * gm.z + bt.z,
                                        (xo[k].w - mu) * rstd * gm.w + bt.w);
        }
    }
}

// =================== launch ====================================================
extern "C" void kernel_launch(void* const* d_in, const int* in_sizes, int n_in,
                              void* d_out, int out_size)
{
    const float* x       = (const float*)d_in[0];
    const float* ln1_g   = (const float*)d_in[1];
    const float* ln1_b   = (const float*)d_in[2];
    const float* ln2_g   = (const float*)d_in[3];
    const float* ln2_b   = (const float*)d_in[4];
    const float* gate_w  = (const float*)d_in[5];
    const float* gate_b  = (const float*)d_in[6];
    const float* value_w = (const float*)d_in[7];
    const float* value_b = (const float*)d_in[8];
    const float* ffn_w1  = (const float*)d_in[9];
    const float* ffn_b1  = (const float*)d_in[10];
    const float* ffn_w2  = (const float*)d_in[11];
    const float* ffn_b2  = (const float*)d_in[12];
    float* out = (float*)d_out;

    __half *h, *h2, *u, *gvwt, *w1t, *w2t, *gv, *xn;
    float *pg, *pgv;
    cudaGetSymbolAddress((void**)&h,    sc_h);
    cudaGetSymbolAddress((void**)&gv,   sc_gv);
    cudaGetSymbolAddress((void**)&xn,   sc_x);
    cudaGetSymbolAddress((void**)&h2,   sc_h2);
    cudaGetSymbolAddress((void**)&u,    sc_u);
    cudaGetSymbolAddress((void**)&pg,   sc_pg);
    cudaGetSymbolAddress((void**)&pgv,  sc_pgv);
    cudaGetSymbolAddress((void**)&gvwt, sc_gvwt);
    cudaGetSymbolAddress((void**)&w1t,  sc_w1t);
    cudaGetSymbolAddress((void**)&w2t,  sc_w2t);

    cudaFuncSetAttribute(gemm_mma<EPI_GV, __half>,   cudaFuncAttributeMaxDynamicSharedMemorySize, GEMM_SMEM);
    cudaFuncSetAttribute(gemm_mma<EPI_GELU, __half>, cudaFuncAttributeMaxDynamicSharedMemorySize, GEMM_SMEM);
    cudaFuncSetAttribute(gemm_mma<EPI_ADD, float>,   cudaFuncAttributeMaxDynamicSharedMemorySize, GEMM_SMEM);

    // 0+1. fused prep: LN1 + all weight transposes (one launch)
    prep_kernel<<<PREP_GRID, 256>>>(x, ln1_g, ln1_b, gate_w, value_w,
                                    ffn_w1, ffn_w2, h, gvwt, w1t, w2t);

    // 2. fused gate|value GEMM -> gv[ROWS, 2D]
    dim3 gridGV(GVS / 128, ROWS / 128);
    gemm_mma<EPI_GV, __half><<<gridGV, 128, GEMM_SMEM>>>(
        h, gvwt, gate_b, value_b, nullptr, gv, ROWS, GVS, D_);

    // 4. memory residual + LN2 (fused)
    cums_partial<<<dim3(B_ * NSEG, D_ / 512), 256>>>(gv, pg, pgv);
    cums_scan<<<(B_ * D_ * 32) / 256, 256>>>(pg, pgv);
    cums_ln2<<<B_ * NSEG, 256>>>(gv, x, pg, pgv, ln2_g, ln2_b, xn, h2);

    // 6. u = gelu(h2 @ W1 + b1)  (fp16 out)
    dim3 gridFF1(4 * D_ / 128, ROWS / 128);
    gemm_mma<EPI_GELU, __half><<<gridFF1, 128, GEMM_SMEM>>>(
        h2, w1t, ffn_b1, nullptr, nullptr, u, ROWS, 4 * D_, D_);

    // 7. out = x_new + u @ W2 + b2
    dim3 gridFF2(D_ / 128, ROWS / 128);
    gemm_mma<EPI_ADD, float><<<gridFF2, 128, GEMM_SMEM>>>(
        u, w2t, ffn_b2, nullptr, xn, out, ROWS, D_, 4 * D_);
}